// round 14
// baseline (speedup 1.0000x reference)
#include <cuda_runtime.h>
#include <cuda_bf16.h>
#include <cuda_fp16.h>
#include <math.h>
#include <stdint.h>

#define B_   4
#define S_   1024
#define E_   1024
#define H_   16
#define HD_  64
#define NBH  64          /* B*H */
#define KP   528         /* padded half-spectrum width */
#define NELEM ((size_t)B_ * S_ * E_)   /* 4M */

/* ---------------- scratch (device globals: no allocations allowed) -------- */
__device__ __nv_bfloat16 g_qh[NELEM],  g_ql[NELEM];
__device__ __nv_bfloat16 g_Wqh[E_*E_], g_Wql[E_*E_];
__device__ __nv_bfloat16 g_Wkh[E_*E_], g_Wkl[E_*E_];
__device__ __nv_bfloat16 g_Wvh[E_*E_], g_Wvl[E_*E_];
__device__ __nv_bfloat16 g_Woh[E_*E_], g_Wol[E_*E_];
__device__ __half        g_Q16[NELEM];                 /* Q single fp16      */
__device__ __half        g_Kh16[NELEM], g_Kl16[NELEM]; /* K split fp16       */
__device__ float         g_V[NELEM];
__device__ __half        g_Vt16[NELEM];                /* V^T single fp16    */
__device__ __half2       g_sc16[(size_t)NBH * 512 * 1024]; /* row-pair scores */
__device__ __half        g_a16[(size_t)NBH * S_ * S_];     /* attn fp16 */
__device__ __nv_bfloat16 g_ch[NELEM],  g_cl[NELEM];
__device__ __half2 g_freq[(size_t)NBH * S_ * KP];
__device__ float2 g_tw[1024];

/* ======================= small helpers ==================================== */
__device__ __forceinline__ uint32_t smem_u32(const void* p) {
    uint32_t a;
    asm("{ .reg .u64 t; cvta.to.shared.u64 t, %1; cvt.u32.u64 %0, t; }"
        : "=r"(a) : "l"(p));
    return a;
}
#define CP16(dst, src) \
    asm volatile("cp.async.cg.shared.global [%0], [%1], 16;" \
                 :: "r"(dst), "l"(src))
#define CP_COMMIT() asm volatile("cp.async.commit_group;" ::: "memory")
#define CP_WAIT1()  asm volatile("cp.async.wait_group 1;" ::: "memory")
#define CP_WAIT0()  asm volatile("cp.async.wait_group 0;" ::: "memory")

__device__ __forceinline__ void mma_bf16(float* d, const uint32_t* a, const uint32_t* b)
{
    asm volatile(
        "mma.sync.aligned.m16n8k16.row.col.f32.bf16.bf16.f32 "
        "{%0,%1,%2,%3}, {%4,%5,%6,%7}, {%8,%9}, {%0,%1,%2,%3};"
        : "+f"(d[0]), "+f"(d[1]), "+f"(d[2]), "+f"(d[3])
        : "r"(a[0]), "r"(a[1]), "r"(a[2]), "r"(a[3]), "r"(b[0]), "r"(b[1]));
}
__device__ __forceinline__ void mma_f16(float* d, const uint32_t* a, const uint32_t* b)
{
    asm volatile(
        "mma.sync.aligned.m16n8k16.row.col.f32.f16.f16.f32 "
        "{%0,%1,%2,%3}, {%4,%5,%6,%7}, {%8,%9}, {%0,%1,%2,%3};"
        : "+f"(d[0]), "+f"(d[1]), "+f"(d[2]), "+f"(d[3])
        : "r"(a[0]), "r"(a[1]), "r"(a[2]), "r"(a[3]), "r"(b[0]), "r"(b[1]));
}

__device__ __forceinline__ int swzt(int row, int ch) {
    return (row << 6) + ((ch ^ ((row >> 1) & 3)) << 4);
}

__device__ __forceinline__ void splitw(float v, __nv_bfloat16& h, __nv_bfloat16& l) {
    h = __float2bfloat16(v);
    l = __float2bfloat16(v - __bfloat162float(h));
}
__device__ __forceinline__ void splitwh(float v, __half& h, __half& l) {
    h = __float2half(v);
    l = __float2half(v - __half2float(h));
}

__device__ __forceinline__ float2 cmul(float2 a, float2 b) {
    return make_float2(a.x * b.x - a.y * b.y, a.x * b.y + a.y * b.x);
}
__device__ __forceinline__ float2 cmulc(float2 a, float2 b) {
    return make_float2(a.x * b.x + a.y * b.y, a.y * b.x - a.x * b.y);
}

/* ============ split convert: fp32 -> bf16 hi + bf16 lo (vectorized) ======= */
__device__ __forceinline__ void split_body(const float* src, __nv_bfloat16* h,
                                           __nv_bfloat16* l, int i)
{
    float4 v = ((const float4*)src)[i];
    __nv_bfloat16 h0, h1, h2, h3, l0, l1, l2, l3;
    splitw(v.x, h0, l0); splitw(v.y, h1, l1);
    splitw(v.z, h2, l2); splitw(v.w, h3, l3);
    uint2 hv, lv;
    hv.x = (uint32_t)__bfloat16_as_ushort(h0) | ((uint32_t)__bfloat16_as_ushort(h1) << 16);
    hv.y = (uint32_t)__bfloat16_as_ushort(h2) | ((uint32_t)__bfloat16_as_ushort(h3) << 16);
    lv.x = (uint32_t)__bfloat16_as_ushort(l0) | ((uint32_t)__bfloat16_as_ushort(l1) << 16);
    lv.y = (uint32_t)__bfloat16_as_ushort(l2) | ((uint32_t)__bfloat16_as_ushort(l3) << 16);
    ((uint2*)h)[i] = hv;
    ((uint2*)l)[i] = lv;
}
__global__ void split_convert(const float* __restrict__ src,
                              __nv_bfloat16* __restrict__ h,
                              __nv_bfloat16* __restrict__ l, int n4)
{
    int i = blockIdx.x * blockDim.x + threadIdx.x;
    if (i < n4) split_body(src, h, l, i);
}
__global__ void split_convert_w4(
    const float* __restrict__ s0, const float* __restrict__ s1,
    const float* __restrict__ s2, const float* __restrict__ s3,
    __nv_bfloat16* __restrict__ h0, __nv_bfloat16* __restrict__ l0,
    __nv_bfloat16* __restrict__ h1, __nv_bfloat16* __restrict__ l1,
    __nv_bfloat16* __restrict__ h2, __nv_bfloat16* __restrict__ l2,
    __nv_bfloat16* __restrict__ h3, __nv_bfloat16* __restrict__ l3)
{
    int i = blockIdx.x * blockDim.x + threadIdx.x;
    int z = blockIdx.z;
    const float* s = (z == 0) ? s0 : (z == 1) ? s1 : (z == 2) ? s2 : s3;
    __nv_bfloat16* h = (z == 0) ? h0 : (z == 1) ? h1 : (z == 2) ? h2 : h3;
    __nv_bfloat16* l = (z == 0) ? l0 : (z == 1) ? l1 : (z == 2) ? l2 : l3;
    split_body(s, h, l, i);
}

/* ====== batched Q/K/V projection GEMM: one launch, grid.z selects W ======= */
__global__ void __launch_bounds__(256, 2) proj_gemm(
    const __nv_bfloat16* __restrict__ Ahg, const __nv_bfloat16* __restrict__ Alg,
    const __nv_bfloat16* __restrict__ W0h, const __nv_bfloat16* __restrict__ W0l,
    const __nv_bfloat16* __restrict__ W1h, const __nv_bfloat16* __restrict__ W1l,
    const __nv_bfloat16* __restrict__ W2h, const __nv_bfloat16* __restrict__ W2l,
    const float* __restrict__ bq, const float* __restrict__ bk,
    const float* __restrict__ bv,
    __half* __restrict__ Q16,
    __half* __restrict__ Kh16, __half* __restrict__ Kl16,
    float* __restrict__ Vo)
{
    constexpr int BM = 128, BN = 128;
    constexpr int ATB = BM * 64, BTB = BN * 64;
    constexpr int BUFS = 2 * ATB + 2 * BTB;
    constexpr int FM = 4, FN = 4;
    constexpr int NIT = 32;

    extern __shared__ char sm[];
    uint32_t smb = smem_u32(sm);

    int tid = threadIdx.x;
    int lane = tid & 31, wid = tid >> 5;
    int wrow = wid >> 2, wcol = wid & 3;
    int m0 = wrow * 64, n0 = wcol * 32;
    int gid = lane >> 2, tig = lane & 3;
    int z = blockIdx.z;

    const __nv_bfloat16* Bhg = (z == 0) ? W0h : (z == 1) ? W1h : W2h;
    const __nv_bfloat16* Blg = (z == 0) ? W0l : (z == 1) ? W1l : W2l;
    const float* bias = (z == 0) ? bq : (z == 1) ? bk : bv;

    const char* A8h = (const char*)Ahg + ((size_t)blockIdx.y * BM * 1024) * 2;
    const char* A8l = (const char*)Alg + ((size_t)blockIdx.y * BM * 1024) * 2;
    const char* B8h = (const char*)Bhg + ((size_t)blockIdx.x * BN * 1024) * 2;
    const char* B8l = (const char*)Blg + ((size_t)blockIdx.x * BN * 1024) * 2;

    auto fill = [&](int bf, int k0) {
        size_t kb = (size_t)k0 * 2;
        uint32_t base = smb + bf * BUFS;
#pragma unroll
        for (int i = tid; i < BM * 4; i += 256) {
            int r = i >> 2, ch = i & 3;
            size_t so = (size_t)r * 2048 + kb + ch * 16;
            CP16(base + swzt(r, ch), A8h + so);
            CP16(base + ATB + swzt(r, ch), A8l + so);
        }
#pragma unroll
        for (int i = tid; i < BN * 4; i += 256) {
            int r = i >> 2, ch = i & 3;
            size_t so = (size_t)r * 2048 + kb + ch * 16;
            CP16(base + 2 * ATB + swzt(r, ch), B8h + so);
            CP16(base + 2 * ATB + BTB + swzt(r, ch), B8l + so);
        }
    };

    float acc[FM][FN][4];
#pragma unroll
    for (int i = 0; i < FM; i++)
#pragma unroll
        for (int j = 0; j < FN; j++)
#pragma unroll
            for (int u = 0; u < 4; u++) acc[i][j][u] = 0.f;

    fill(0, 0);
    CP_COMMIT();
    fill(1, 32);
    CP_COMMIT();

    for (int it = 0; it < NIT; ++it) {
        if (it + 1 < NIT) { CP_WAIT1(); } else { CP_WAIT0(); }
        __syncthreads();
        int buf = it % 3;
        const char* pAh = sm + buf * BUFS;
        const char* pAl = pAh + ATB;
        const char* pBh = pAh + 2 * ATB;
        const char* pBl = pBh + BTB;
#pragma unroll
        for (int ks = 0; ks < 2; ks++) {
            uint32_t bhf[FN][2], blf[FN][2];
#pragma unroll
            for (int fn = 0; fn < FN; fn++) {
                int br = n0 + fn * 8 + gid;
                int o0 = swzt(br, ks * 2) + tig * 4;
                int o1 = swzt(br, ks * 2 + 1) + tig * 4;
                bhf[fn][0] = *(const uint32_t*)(pBh + o0);
                bhf[fn][1] = *(const uint32_t*)(pBh + o1);
                blf[fn][0] = *(const uint32_t*)(pBl + o0);
                blf[fn][1] = *(const uint32_t*)(pBl + o1);
            }
#pragma unroll
            for (int fm = 0; fm < FM; fm++) {
                int ar0 = m0 + fm * 16 + gid, ar8 = ar0 + 8;
                int o00 = swzt(ar0, ks * 2) + tig * 4;
                int o80 = swzt(ar8, ks * 2) + tig * 4;
                int o01 = swzt(ar0, ks * 2 + 1) + tig * 4;
                int o81 = swzt(ar8, ks * 2 + 1) + tig * 4;
                uint32_t ahf[4], alf[4];
                ahf[0] = *(const uint32_t*)(pAh + o00);
                ahf[1] = *(const uint32_t*)(pAh + o80);
                ahf[2] = *(const uint32_t*)(pAh + o01);
                ahf[3] = *(const uint32_t*)(pAh + o81);
                alf[0] = *(const uint32_t*)(pAl + o00);
                alf[1] = *(const uint32_t*)(pAl + o80);
                alf[2] = *(const uint32_t*)(pAl + o01);
                alf[3] = *(const uint32_t*)(pAl + o81);
#pragma unroll
                for (int fn = 0; fn < FN; fn++) {
                    mma_bf16(acc[fm][fn], ahf, bhf[fn]);
                    mma_bf16(acc[fm][fn], ahf, blf[fn]);
                    mma_bf16(acc[fm][fn], alf, bhf[fn]);
                }
            }
        }
        if (it + 2 < NIT) {
            fill((it + 2) % 3, (it + 2) * 32);
            CP_COMMIT();
        }
    }

#pragma unroll
    for (int fm = 0; fm < FM; fm++) {
        size_t r0 = (size_t)blockIdx.y * BM + m0 + fm * 16 + gid;
#pragma unroll
        for (int fn = 0; fn < FN; fn++) {
            int cgl = blockIdx.x * BN + n0 + fn * 8 + tig * 2;
            float b0 = bias[cgl], b1 = bias[cgl + 1];
            float v00 = acc[fm][fn][0] + b0;
            float v01 = acc[fm][fn][1] + b1;
            float v10 = acc[fm][fn][2] + b0;
            float v11 = acc[fm][fn][3] + b1;
            if (z == 2) {
                *(float2*)&Vo[r0 * 1024 + cgl] = make_float2(v00, v01);
                *(float2*)&Vo[(r0 + 8) * 1024 + cgl] = make_float2(v10, v11);
            } else if (z == 0) {
                __half2 p0 = __floats2half2_rn(v00, v01);
                __half2 p1 = __floats2half2_rn(v10, v11);
                *(uint32_t*)&Q16[r0 * 1024 + cgl] = *(uint32_t*)&p0;
                *(uint32_t*)&Q16[(r0 + 8) * 1024 + cgl] = *(uint32_t*)&p1;
            } else {
                __half h00, h01, h10, h11, l00, l01, l10, l11;
                splitwh(v00, h00, l00); splitwh(v01, h01, l01);
                splitwh(v10, h10, l10); splitwh(v11, h11, l11);
                uint32_t hv0 = (uint32_t)__half_as_ushort(h00) | ((uint32_t)__half_as_ushort(h01) << 16);
                uint32_t lv0 = (uint32_t)__half_as_ushort(l00) | ((uint32_t)__half_as_ushort(l01) << 16);
                uint32_t hv1 = (uint32_t)__half_as_ushort(h10) | ((uint32_t)__half_as_ushort(h11) << 16);
                uint32_t lv1 = (uint32_t)__half_as_ushort(l10) | ((uint32_t)__half_as_ushort(l11) << 16);
                *(uint32_t*)&Kh16[r0 * 1024 + cgl] = hv0;
                *(uint32_t*)&Kl16[r0 * 1024 + cgl] = lv0;
                *(uint32_t*)&Kh16[(r0 + 8) * 1024 + cgl] = hv1;
                *(uint32_t*)&Kl16[(r0 + 8) * 1024 + cgl] = lv1;
            }
        }
    }
}

/* == generic tensor-core GEMM (scores / AV / out), 3-stage pipeline ======== */
template<int MODE, int EPI, int KIND, int BN, int WROWS, int WCOLS, int KTOT>
__global__ void __launch_bounds__(256, 2) mma_gemm(
    const __nv_bfloat16* __restrict__ Ahg, const __nv_bfloat16* __restrict__ Alg,
    const __nv_bfloat16* __restrict__ Bhg, const __nv_bfloat16* __restrict__ Blg,
    const float* __restrict__ bias, void* __restrict__ Cp, void* __restrict__ C2p,
    float oscale)
{
    constexpr int BM = 128;
    constexpr int ATB = BM * 64;
    constexpr int BTB = BN * 64;
    constexpr int ABYTES = (KIND >= 1 ? 1 : 2) * ATB;
    constexpr int NB = (KIND == 2) ? 1 : 2;
    constexpr int BUFS = ABYTES + NB * BTB;
    constexpr int WTM = BM / WROWS, WTN = BN / WCOLS;
    constexpr int FM = WTM / 16, FN = WTN / 8;
    constexpr int NIT = KTOT / 32;

    extern __shared__ char sm[];
    uint32_t smb = smem_u32(sm);

    int tid = threadIdx.x;
    int lane = tid & 31, wid = tid >> 5;
    int wrow = wid / WCOLS, wcol = wid % WCOLS;
    int m0 = wrow * WTM, n0 = wcol * WTN;
    int gid = lane >> 2, tig = lane & 3;

    size_t offA = 0, offB = 0, offC = 0, offP = 0;
    if (MODE == 1) {
        int z = blockIdx.z;
        size_t ho = (size_t)(z >> 4) * S_ * E_ + (size_t)(z & 15) * HD_;
        offA = ho; offB = ho;
        offP = (size_t)z * 512 * 1024;
    } else if (MODE == 2) {
        int z = blockIdx.z;
        offA = (size_t)z * S_ * S_;
        offB = (size_t)z * HD_ * S_;
        offC = (size_t)(z >> 4) * S_ * E_ + (size_t)(z & 15) * HD_;
    }
    const char* A8h = (const char*)Ahg + (offA + (size_t)blockIdx.y * BM * 1024) * 2;
    const char* A8l = (const char*)Alg + (offA + (size_t)blockIdx.y * BM * 1024) * 2;
    const char* B8h = (const char*)Bhg + (offB + (size_t)blockIdx.x * BN * 1024) * 2;
    const char* B8l = (const char*)Blg + (offB + (size_t)blockIdx.x * BN * 1024) * 2;

    auto fill = [&](int bf, int k0) {
        size_t kb = (size_t)k0 * 2;
        uint32_t base = smb + bf * BUFS;
#pragma unroll
        for (int i = tid; i < BM * 4; i += 256) {
            int r = i >> 2, ch = i & 3;
            size_t so = (size_t)r * 2048 + kb + ch * 16;
            CP16(base + swzt(r, ch), A8h + so);
            if (KIND == 0) CP16(base + ATB + swzt(r, ch), A8l + so);
        }
#pragma unroll
        for (int i = tid; i < BN * 4; i += 256) {
            int r = i >> 2, ch = i & 3;
            size_t so = (size_t)r * 2048 + kb + ch * 16;
            CP16(base + ABYTES + swzt(r, ch), B8h + so);
            if (KIND != 2) CP16(base + ABYTES + BTB + swzt(r, ch), B8l + so);
        }
    };

    float acc[FM][FN][4];
#pragma unroll
    for (int i = 0; i < FM; i++)
#pragma unroll
        for (int j = 0; j < FN; j++)
#pragma unroll
            for (int u = 0; u < 4; u++) acc[i][j][u] = 0.f;

    fill(0, 0);
    CP_COMMIT();
    if (NIT > 1) fill(1, 32);
    CP_COMMIT();

    for (int it = 0; it < NIT; ++it) {
        if (it + 1 < NIT) { CP_WAIT1(); } else { CP_WAIT0(); }
        __syncthreads();
        int buf = it % 3;
        const char* pAh = sm + buf * BUFS;
        const char* pAl = pAh + ATB;
        const char* pBh = pAh + ABYTES;
        const char* pBl = pBh + BTB;
#pragma unroll
        for (int ks = 0; ks < 2; ks++) {
            uint32_t bhf[FN][2], blf[FN][2];
#pragma unroll
            for (int fn = 0; fn < FN; fn++) {
                int br = n0 + fn * 8 + gid;
                int o0 = swzt(br, ks * 2) + tig * 4;
                int o1 = swzt(br, ks * 2 + 1) + tig * 4;
                bhf[fn][0] = *(const uint32_t*)(pBh + o0);
                bhf[fn][1] = *(const uint32_t*)(pBh + o1);
                if (KIND != 2) {
                    blf[fn][0] = *(const uint32_t*)(pBl + o0);
                    blf[fn][1] = *(const uint32_t*)(pBl + o1);
                }
            }
#pragma unroll
            for (int fm = 0; fm < FM; fm++) {
                int ar0 = m0 + fm * 16 + gid, ar8 = ar0 + 8;
                int o00 = swzt(ar0, ks * 2) + tig * 4;
                int o80 = swzt(ar8, ks * 2) + tig * 4;
                int o01 = swzt(ar0, ks * 2 + 1) + tig * 4;
                int o81 = swzt(ar8, ks * 2 + 1) + tig * 4;
                uint32_t ahf[4];
                ahf[0] = *(const uint32_t*)(pAh + o00);
                ahf[1] = *(const uint32_t*)(pAh + o80);
                ahf[2] = *(const uint32_t*)(pAh + o01);
                ahf[3] = *(const uint32_t*)(pAh + o81);
                if (KIND == 0) {
                    uint32_t alf[4];
                    alf[0] = *(const uint32_t*)(pAl + o00);
                    alf[1] = *(const uint32_t*)(pAl + o80);
                    alf[2] = *(const uint32_t*)(pAl + o01);
                    alf[3] = *(const uint32_t*)(pAl + o81);
#pragma unroll
                    for (int fn = 0; fn < FN; fn++) {
                        mma_bf16(acc[fm][fn], ahf, bhf[fn]);
                        mma_bf16(acc[fm][fn], ahf, blf[fn]);
                        mma_bf16(acc[fm][fn], alf, bhf[fn]);
                    }
                } else if (KIND == 1) {
#pragma unroll
                    for (int fn = 0; fn < FN; fn++) {
                        mma_f16(acc[fm][fn], ahf, bhf[fn]);
                        mma_f16(acc[fm][fn], ahf, blf[fn]);
                    }
                } else {
#pragma unroll
                    for (int fn = 0; fn < FN; fn++)
                        mma_f16(acc[fm][fn], ahf, bhf[fn]);
                }
            }
        }
        if (it + 2 < NIT) {
            fill((it + 2) % 3, (it + 2) * 32);
            CP_COMMIT();
        }
    }

#pragma unroll
    for (int fm = 0; fm < FM; fm++) {
        size_t r0 = (size_t)blockIdx.y * BM + m0 + fm * 16 + gid;
#pragma unroll
        for (int fn = 0; fn < FN; fn++) {
            int cgl = blockIdx.x * BN + n0 + fn * 8 + tig * 2;
            float v00 = acc[fm][fn][0] * oscale;
            float v01 = acc[fm][fn][1] * oscale;
            float v10 = acc[fm][fn][2] * oscale;
            float v11 = acc[fm][fn][3] * oscale;
            if (EPI == 4) {
                float q00 = __shfl_xor_sync(0xffffffffu, v00, 4);
                float q01 = __shfl_xor_sync(0xffffffffu, v01, 4);
                float q10 = __shfl_xor_sync(0xffffffffu, v10, 4);
                float q11 = __shfl_xor_sync(0xffffffffu, v11, 4);
                if (!(gid & 1)) {
                    __half2* SC = (__half2*)Cp;
                    __half2 a0 = __floats2half2_rn(v00, q00);
                    __half2 a1 = __floats2half2_rn(v01, q01);
                    __half2 b0 = __floats2half2_rn(v10, q10);
                    __half2 b1 = __floats2half2_rn(v11, q11);
                    uint2 pk0 = make_uint2(*(uint32_t*)&a0, *(uint32_t*)&a1);
                    uint2 pk1 = make_uint2(*(uint32_t*)&b0, *(uint32_t*)&b1);
                    *(uint2*)&SC[offP + (r0 >> 1) * 1024 + cgl] = pk0;
                    *(uint2*)&SC[offP + ((r0 + 8) >> 1) * 1024 + cgl] = pk1;
                }
            } else if (EPI == 0) {
                float b0 = bias[cgl], b1 = bias[cgl + 1];
                float* C = (float*)Cp;
                *(float2*)&C[offC + r0 * 1024 + cgl] = make_float2(v00 + b0, v01 + b1);
                *(float2*)&C[offC + (r0 + 8) * 1024 + cgl] = make_float2(v10 + b0, v11 + b1);
            } else {
                __nv_bfloat16* Ch = (__nv_bfloat16*)Cp;
                __nv_bfloat16* Cl = (__nv_bfloat16*)C2p;
                __nv_bfloat16 h00, h01, h10, h11, l00, l01, l10, l11;
                splitw(v00, h00, l00); splitw(v01, h01, l01);
                splitw(v10, h10, l10); splitw(v11, h11, l11);
                uint32_t hv0 = (uint32_t)__bfloat16_as_ushort(h00) | ((uint32_t)__bfloat16_as_ushort(h01) << 16);
                uint32_t lv0 = (uint32_t)__bfloat16_as_ushort(l00) | ((uint32_t)__bfloat16_as_ushort(l01) << 16);
                uint32_t hv1 = (uint32_t)__bfloat16_as_ushort(h10) | ((uint32_t)__bfloat16_as_ushort(h11) << 16);
                uint32_t lv1 = (uint32_t)__bfloat16_as_ushort(l10) | ((uint32_t)__bfloat16_as_ushort(l11) << 16);
                *(uint32_t*)&Ch[offC + r0 * 1024 + cgl] = hv0;
                *(uint32_t*)&Cl[offC + r0 * 1024 + cgl] = lv0;
                *(uint32_t*)&Ch[offC + (r0 + 8) * 1024 + cgl] = hv1;
                *(uint32_t*)&Cl[offC + (r0 + 8) * 1024 + cgl] = lv1;
            }
        }
    }
}

/* ===== Vt[z][d][k] = V[b][k][h*64+d], written single fp16 ================= */
__global__ void transpose_v(const float* __restrict__ V, __half* __restrict__ Vt)
{
    __shared__ float tile[32][33];
    int z = blockIdx.z;
    int b = z >> 4, h = z & 15;
    int k0 = blockIdx.x * 32, d0 = blockIdx.y * 32;
    int tx = threadIdx.x, ty = threadIdx.y;
#pragma unroll
    for (int i = 0; i < 4; i++)
        tile[ty + i * 8][tx] =
            V[((size_t)b * S_ + k0 + ty + i * 8) * E_ + h * HD_ + d0 + tx];
    __syncthreads();
#pragma unroll
    for (int i = 0; i < 4; i++) {
        size_t o = ((size_t)z * HD_ + d0 + ty + i * 8) * S_ + k0 + tx;
        Vt[o] = __float2half(tile[tx][ty + i * 8]);
    }
}

/* ===================== twiddle init ======================================= */
__global__ void init_twiddles(float2* tw)
{
    int j = blockIdx.x * blockDim.x + threadIdx.x;
    if (j < 1024) {
        float ang = -6.28318530717958647692f * (float)j / 1024.0f;
        tw[j] = make_float2(cosf(ang), sinf(ang));
    }
}

/* ============== in-register 32-pt FFT (DIF, natural order out) ============ */
template<bool INV>
__device__ __forceinline__ void fft32r(float2* v)
{
    const float C[16] = {
        1.f, 0.980785280403230f, 0.923879532511287f, 0.831469612302545f,
        0.707106781186548f, 0.555570233019602f, 0.382683432365090f, 0.195090322016128f,
        0.f, -0.195090322016128f, -0.382683432365090f, -0.555570233019602f,
        -0.707106781186548f, -0.831469612302545f, -0.923879532511287f, -0.980785280403230f };
    const float Sn[16] = {
        0.f, 0.195090322016128f, 0.382683432365090f, 0.555570233019602f,
        0.707106781186548f, 0.831469612302545f, 0.923879532511287f, 0.980785280403230f,
        1.f, 0.980785280403230f, 0.923879532511287f, 0.831469612302545f,
        0.707106781186548f, 0.555570233019602f, 0.382683432365090f, 0.195090322016128f };
#pragma unroll
    for (int h = 16; h >= 1; h >>= 1) {
#pragma unroll
        for (int b = 0; b < 32; b += 2 * h) {
#pragma unroll
            for (int j = 0; j < h; j++) {
                int e = j * (16 / h);
                float tc = C[e];
                float ts = INV ? Sn[e] : -Sn[e];
                float2 a = v[b + j], bb = v[b + j + h];
                v[b + j] = make_float2(a.x + bb.x, a.y + bb.y);
                float dx = a.x - bb.x, dy = a.y - bb.y;
                v[b + j + h] = make_float2(dx * tc - dy * ts, dx * ts + dy * tc);
            }
        }
    }
#pragma unroll
    for (int i = 0; i < 32; i++) {
        int r = ((i & 1) << 4) | ((i & 2) << 2) | (i & 4) | ((i & 8) >> 2) | ((i & 16) >> 4);
        if (r > i) { float2 tmp = v[i]; v[i] = v[r]; v[r] = tmp; }
    }
}

/* ====== pass 1: warp fwd FFT of packed fp16 row pairs -> half spectra ===== */
__global__ void __launch_bounds__(128) fft_rows_fwd_w(
    const __half2* __restrict__ sc, __half2* __restrict__ Y,
    const float2* __restrict__ twg)
{
    __shared__ __align__(16) float pat[4 * 2112];
    int t = threadIdx.x & 31, w = threadIdx.x >> 5;
    float* pre = pat + w * 2112;
    float* pim = pre + 1056;
    size_t p = (size_t)blockIdx.x * 4 + w;
    const __half2* r01 = sc + p * 1024;

    float2 v[32];
#pragma unroll
    for (int i2 = 0; i2 < 32; i2++)
        v[i2] = __half22float2(r01[t + 32 * i2]);
    fft32r<false>(v);
#pragma unroll
    for (int k2 = 1; k2 < 32; k2++)
        v[k2] = cmul(v[k2], twg[(t * k2) & 1023]);
#pragma unroll
    for (int k2 = 0; k2 < 32; k2++) {
        pre[t * 33 + k2] = v[k2].x;
        pim[t * 33 + k2] = v[k2].y;
    }
    __syncwarp();
#pragma unroll
    for (int i1 = 0; i1 < 32; i1++)
        v[i1] = make_float2(pre[i1 * 33 + t], pim[i1 * 33 + t]);
    __syncwarp();
    fft32r<false>(v);
#pragma unroll
    for (int k1 = 0; k1 < 32; k1++) {
        pre[k1 * 33 + t] = v[k1].x;
        pim[k1 * 33 + t] = v[k1].y;
    }
    __syncwarp();

    __half2* y0 = Y + (size_t)(2 * p) * KP;
    __half2* y1 = y0 + KP;
#pragma unroll
    for (int u = 0; u <= 16; u++) {
        int k = t + 32 * u;
        if (u < 16 || t == 0) {
            int idx = u * 33 + t;
            float2 Xk = make_float2(pre[idx], pim[idx]);
            int m = (1024 - k) & 1023;
            int midx = (m >> 5) * 33 + (m & 31);
            float2 Xm = make_float2(pre[midx], pim[midx]);
            y0[k] = __floats2half2_rn(0.5f * (Xk.x + Xm.x), 0.5f * (Xk.y - Xm.y));
            y1[k] = __floats2half2_rn(0.5f * (Xk.y + Xm.y), 0.5f * (Xm.x - Xk.x));
        }
    }
}

/* ===== pass 2: warp-level col FFT + real cos-filter + col IFFT =========== */
__global__ void __launch_bounds__(128) fft_cols_w(
    __half2* __restrict__ Y, const float* __restrict__ alpha_p,
    const float2* __restrict__ twg)
{
    __shared__ __align__(16) float sm[10240];   /* slab 2x5120 / patches 4x2112 */
    float* slab_re = sm;
    float* slab_im = sm + 5120;
    int tid = threadIdx.x;
    int t = tid & 31, w = tid >> 5;
    int z = blockIdx.y;
    int kbase = blockIdx.x * 4;
    __half2* base = Y + (size_t)z * S_ * KP + kbase;

#pragma unroll 8
    for (int idx = tid; idx < 4096; idx += 128) {
        int q = idx >> 2, c = idx & 3;
        float2 val = __half22float2(base[(size_t)q * KP + c]);
        slab_re[q * 5 + c] = val.x;
        slab_im[q * 5 + c] = val.y;
    }
    __syncthreads();

    float2 v[32];
#pragma unroll
    for (int i2 = 0; i2 < 32; i2++) {
        int q = t + 32 * i2;
        v[i2] = make_float2(slab_re[q * 5 + w], slab_im[q * 5 + w]);
    }
    __syncthreads();
    float* pre = sm + w * 2112;
    float* pim = pre + 1056;

    fft32r<false>(v);
#pragma unroll
    for (int k2 = 1; k2 < 32; k2++)
        v[k2] = cmul(v[k2], twg[(t * k2) & 1023]);
#pragma unroll
    for (int k2 = 0; k2 < 32; k2++) {
        pre[t * 33 + k2] = v[k2].x;
        pim[t * 33 + k2] = v[k2].y;
    }
    __syncwarp();
#pragma unroll
    for (int i1 = 0; i1 < 32; i1++)
        v[i1] = make_float2(pre[i1 * 33 + t], pim[i1 * 33 + t]);
    __syncwarp();
    fft32r<false>(v);

    float alpha = *alpha_p;
#pragma unroll
    for (int k1 = 0; k1 < 32; k1++) {
        float mag = sqrtf(v[k1].x * v[k1].x + v[k1].y * v[k1].y);
        float g = __cosf(alpha * atanf(__logf(mag + 1e-10f)));
        v[k1].x *= g; v[k1].y *= g;
    }

    fft32r<true>(v);
#pragma unroll
    for (int i1 = 1; i1 < 32; i1++)
        v[i1] = cmulc(v[i1], twg[(t * i1) & 1023]);
#pragma unroll
    for (int i1 = 0; i1 < 32; i1++) {
        pre[t * 33 + i1] = v[i1].x;
        pim[t * 33 + i1] = v[i1].y;
    }
    __syncwarp();
#pragma unroll
    for (int k2 = 0; k2 < 32; k2++)
        v[k2] = make_float2(pre[k2 * 33 + t], pim[k2 * 33 + t]);
    __syncwarp();
    fft32r<true>(v);

    __syncthreads();
    const float scl = 1.0f / 1024.0f;
#pragma unroll
    for (int i2 = 0; i2 < 32; i2++) {
        int q = t + 32 * i2;
        slab_re[q * 5 + w] = v[i2].x * scl;
        slab_im[q * 5 + w] = v[i2].y * scl;
    }
    __syncthreads();
#pragma unroll 8
    for (int idx = tid; idx < 4096; idx += 128) {
        int q = idx >> 2, c = idx & 3;
        if (kbase + c < 513)
            base[(size_t)q * KP + c] =
                __floats2half2_rn(slab_re[q * 5 + c], slab_im[q * 5 + c]);
    }
}

/* == pass 3: warp c2r inverse + warp softmax (in-place, low reg pressure) == */
__global__ void __launch_bounds__(128) fft_rows_inv_softmax_w(
    const __half2* __restrict__ Y, __half* __restrict__ out16,
    const float2* __restrict__ twg)
{
    __shared__ __align__(16) float pat[4 * 2112];
    int t = threadIdx.x & 31, w = threadIdx.x >> 5;
    float* pre = pat + w * 2112;
    float* pim = pre + 1056;
    size_t p = (size_t)blockIdx.x * 4 + w;
    const __half2* y0 = Y + (size_t)(2 * p) * KP;
    const __half2* y1 = y0 + KP;

#pragma unroll
    for (int u = 0; u <= 16; u++) {
        int k = t + 32 * u;
        if (u < 16 || t == 0) {
            float2 h0 = __half22float2(y0[k]);
            float2 h1 = __half22float2(y1[k]);
            int idx = u * 33 + t;
            pre[idx] = h0.x - h1.y;
            pim[idx] = h0.y + h1.x;
            if (k >= 1 && k < 512) {
                int m = 1024 - k;
                int midx = (m >> 5) * 33 + (m & 31);
                pre[midx] = h0.x + h1.y;
                pim[midx] = h1.x - h0.y;
            }
        }
    }
    __syncwarp();
    float2 v[32];
#pragma unroll
    for (int k1 = 0; k1 < 32; k1++)
        v[k1] = make_float2(pre[k1 * 33 + t], pim[k1 * 33 + t]);
    __syncwarp();
    fft32r<true>(v);
#pragma unroll
    for (int i1 = 1; i1 < 32; i1++)
        v[i1] = cmulc(v[i1], twg[(t * i1) & 1023]);
#pragma unroll
    for (int i1 = 0; i1 < 32; i1++) {
        pre[t * 33 + i1] = v[i1].x;
        pim[t * 33 + i1] = v[i1].y;
    }
    __syncwarp();
#pragma unroll
    for (int k2 = 0; k2 < 32; k2++)
        v[k2] = make_float2(pre[k2 * 33 + t], pim[k2 * 33 + t]);
    __syncwarp();
    fft32r<true>(v);

    const float scl = 1.0f / 1024.0f;
    float m0 = -1e30f, m1 = -1e30f;
#pragma unroll
    for (int i2 = 0; i2 < 32; i2++) {
        v[i2].x *= scl; v[i2].y *= scl;
        m0 = fmaxf(m0, v[i2].x); m1 = fmaxf(m1, v[i2].y);
    }
#pragma unroll
    for (int o = 16; o; o >>= 1) {
        m0 = fmaxf(m0, __shfl_xor_sync(0xffffffffu, m0, o));
        m1 = fmaxf(m1, __shfl_xor_sync(0xffffffffu, m1, o));
    }
    /* exp in place: pre-softmax values dead after max reduction */
    float s0 = 0.f, s1 = 0.f;
#pragma unroll
    for (int i2 = 0; i2 < 32; i2++) {
        v[i2].x = __expf(v[i2].x - m0);
        v[i2].y = __expf(v[i2].y - m1);
        s0 += v[i2].x; s1 += v[i2].y;
    }
#pragma unroll
    for (int o = 16; o; o >>= 1) {
        s0 += __shfl_xor_sync(0xffffffffu, s0, o);
        s1 += __shfl_xor_sync(0xffffffffu, s1, o);
    }
    float inv0 = 1.0f / s0, inv1 = 1.0f / s1;
    __syncwarp();
    __half* hb = (__half*)pre;
#pragma unroll
    for (int i2 = 0; i2 < 32; i2++) {
        int col = t + 32 * i2;
        hb[col] = __float2half(v[i2].x * inv0);
        hb[1024 + col] = __float2half(v[i2].y * inv1);
    }
    __syncwarp();
    uint4* dst = (uint4*)(out16 + (size_t)(2 * p) * 1024);
    const uint4* srcv = (const uint4*)hb;
#pragma unroll
    for (int j = t; j < 256; j += 32) dst[j] = srcv[j];
}

/* ============================== launcher =================================== */
extern "C" void kernel_launch(void* const* d_in, const int* in_sizes, int n_in,
                              void* d_out, int out_size)
{
    const float* query = (const float*)d_in[0];
    const float* Wq    = (const float*)d_in[1];
    const float* bq    = (const float*)d_in[2];
    const float* Wk    = (const float*)d_in[3];
    const float* bk    = (const float*)d_in[4];
    const float* Wv    = (const float*)d_in[5];
    const float* bv    = (const float*)d_in[6];
    const float* Wo    = (const float*)d_in[7];
    const float* bo    = (const float*)d_in[8];
    const float* alpha = (const float*)d_in[9];
    float* out = (float*)d_out;

    __nv_bfloat16 *pqh, *pql, *pWqh, *pWql, *pWkh, *pWkl, *pWvh, *pWvl, *pWoh, *pWol;
    __nv_bfloat16 *pch, *pcl;
    __half *pQ16, *pKh16, *pKl16, *pVt16, *pA16;
    __half2 *pSc16, *pFreq;
    float *pV;
    float2 *pTw;
    cudaGetSymbolAddress((void**)&pqh, g_qh);   cudaGetSymbolAddress((void**)&pql, g_ql);
    cudaGetSymbolAddress((void**)&pWqh, g_Wqh); cudaGetSymbolAddress((void**)&pWql, g_Wql);
    cudaGetSymbolAddress((void**)&pWkh, g_Wkh); cudaGetSymbolAddress((void**)&pWkl, g_Wkl);
    cudaGetSymbolAddress((void**)&pWvh, g_Wvh); cudaGetSymbolAddress((void**)&pWvl, g_Wvl);
    cudaGetSymbolAddress((void**)&pWoh, g_Woh); cudaGetSymbolAddress((void**)&pWol, g_Wol);
    cudaGetSymbolAddress((void**)&pQ16, g_Q16);
    cudaGetSymbolAddress((void**)&pKh16, g_Kh16);
    cudaGetSymbolAddress((void**)&pKl16, g_Kl16);
    cudaGetSymbolAddress((void**)&pVt16, g_Vt16);
    cudaGetSymbolAddress((void**)&pch, g_ch);   cudaGetSymbolAddress((void**)&pcl, g_cl);
    cudaGetSymbolAddress((void**)&pV, g_V);
    cudaGetSymbolAddress((void**)&pSc16, g_sc16);
    cudaGetSymbolAddress((void**)&pA16, g_a16);
    cudaGetSymbolAddress((void**)&pFreq, g_freq);
    cudaGetSymbolAddress((void**)&pTw, g_tw);

    const int SM_P = 3 * (2 * 8192 + 2 * 8192);   /* 98304 */
    const int SM_S = 3 * (1 * 8192 + 2 * 8192);   /* 73728 */
    const int SM_A = 3 * (1 * 8192 + 1 * 4096);   /* 36864 */
    cudaFuncSetAttribute((const void*)proj_gemm,
                         cudaFuncAttributeMaxDynamicSharedMemorySize, SM_P);
    cudaFuncSetAttribute((const void*)mma_gemm<0, 0, 0, 128, 2, 4, 1024>,
                         cudaFuncAttributeMaxDynamicSharedMemorySize, SM_P);
    cudaFuncSetAttribute((const void*)mma_gemm<1, 4, 1, 128, 2, 4, 64>,
                         cudaFuncAttributeMaxDynamicSharedMemorySize, SM_S);
    cudaFuncSetAttribute((const void*)mma_gemm<2, 3, 2, 64, 4, 2, 1024>,
                         cudaFuncAttributeMaxDynamicSharedMemorySize, SM_A);

    init_twiddles<<<4, 256>>>(pTw);

    split_convert<<<(int)(NELEM / 4 / 256), 256>>>(query, pqh, pql, (int)(NELEM / 4));
    split_convert_w4<<<dim3(E_ * E_ / 4 / 256, 1, 4), 256>>>(
        Wq, Wk, Wv, Wo, pWqh, pWql, pWkh, pWkl, pWvh, pWvl, pWoh, pWol);

    dim3 gp3(E_ / 128, (B_ * S_) / 128, 3);
    proj_gemm<<<gp3, 256, SM_P>>>(pqh, pql,
                                  pWqh, pWql, pWkh, pWkl, pWvh, pWvl,
                                  bq, bk, bv,
                                  pQ16, pKh16, pKl16, pV);

    transpose_v<<<dim3(32, 2, NBH), dim3(32, 8)>>>(pV, pVt16);

    dim3 gs(S_ / 128, S_ / 128, NBH);
    mma_gemm<1, 4, 1, 128, 2, 4, 64><<<gs, 256, SM_S>>>(
        (const __nv_bfloat16*)pQ16, 0,
        (const __nv_bfloat16*)pKh16, (const __nv_bfloat16*)pKl16,
        0, pSc16, 0, 0.125f);

    fft_rows_fwd_w<<<NBH * S_ / 2 / 4, 128>>>(pSc16, pFreq, pTw);

    fft_cols_w<<<dim3(129, NBH), 128>>>(pFreq, alpha, pTw);

    fft_rows_inv_softmax_w<<<NBH * S_ / 2 / 4, 128>>>(pFreq, pA16, pTw);

    dim3 ga(1, S_ / 128, NBH);
    mma_gemm<2, 3, 2, 64, 4, 2, 1024><<<ga, 256, SM_A>>>(
        (const __nv_bfloat16*)pA16, 0,
        (const __nv_bfloat16*)pVt16, 0, 0, pch, pcl, 1.0f);

    dim3 gp(E_ / 128, (B_ * S_) / 128, 1);
    mma_gemm<0, 0, 0, 128, 2, 4, 1024><<<gp, 256, SM_P>>>(pch, pcl, pWoh, pWol, bo, out, 0, 1.0f);
}

// round 15
// speedup vs baseline: 1.0615x; 1.0615x over previous
#include <cuda_runtime.h>
#include <cuda_fp16.h>
#include <math.h>
#include <stdint.h>

#define B_   4
#define S_   1024
#define E_   1024
#define H_   16
#define HD_  64
#define NBH  64          /* B*H */
#define KP   528         /* padded half-spectrum width */
#define NELEM ((size_t)B_ * S_ * E_)   /* 4M */

/* ---------------- scratch (device globals: no allocations allowed) -------- */
__device__ __half g_qh[NELEM],  g_ql[NELEM];          /* query fp16 split   */
__device__ __half g_Wqh[E_*E_], g_Wql[E_*E_];
__device__ __half g_Wkh[E_*E_], g_Wkl[E_*E_];
__device__ __half g_Wvh[E_*E_], g_Wvl[E_*E_];
__device__ __half g_Woh[E_*E_], g_Wol[E_*E_];
__device__ __half g_Q16[NELEM];                       /* Q single fp16      */
__device__ __half g_Kh16[NELEM], g_Kl16[NELEM];       /* K split fp16       */
__device__ float  g_V[NELEM];
__device__ __half g_Vt16[NELEM];                      /* V^T single fp16    */
__device__ __half2 g_sc16[(size_t)NBH * 512 * 1024];  /* row-pair scores    */
__device__ __half g_a16[(size_t)NBH * S_ * S_];       /* attn fp16          */
__device__ __half g_ch[NELEM],  g_cl[NELEM];          /* ctx fp16 split     */
__device__ __half2 g_freq[(size_t)NBH * S_ * KP];
__device__ float2 g_tw[1024];

/* ======================= small helpers ==================================== */
__device__ __forceinline__ uint32_t smem_u32(const void* p) {
    uint32_t a;
    asm("{ .reg .u64 t; cvta.to.shared.u64 t, %1; cvt.u32.u64 %0, t; }"
        : "=r"(a) : "l"(p));
    return a;
}
#define CP16(dst, src) \
    asm volatile("cp.async.cg.shared.global [%0], [%1], 16;" \
                 :: "r"(dst), "l"(src))
#define CP_COMMIT() asm volatile("cp.async.commit_group;" ::: "memory")
#define CP_WAIT1()  asm volatile("cp.async.wait_group 1;" ::: "memory")
#define CP_WAIT0()  asm volatile("cp.async.wait_group 0;" ::: "memory")

__device__ __forceinline__ void mma_f16(float* d, const uint32_t* a, const uint32_t* b)
{
    asm volatile(
        "mma.sync.aligned.m16n8k16.row.col.f32.f16.f16.f32 "
        "{%0,%1,%2,%3}, {%4,%5,%6,%7}, {%8,%9}, {%0,%1,%2,%3};"
        : "+f"(d[0]), "+f"(d[1]), "+f"(d[2]), "+f"(d[3])
        : "r"(a[0]), "r"(a[1]), "r"(a[2]), "r"(a[3]), "r"(b[0]), "r"(b[1]));
}

__device__ __forceinline__ int swzt(int row, int ch) {
    return (row << 6) + ((ch ^ ((row >> 1) & 3)) << 4);
}

__device__ __forceinline__ void splitwh(float v, __half& h, __half& l) {
    h = __float2half(v);
    l = __float2half(v - __half2float(h));
}

__device__ __forceinline__ float2 cmul(float2 a, float2 b) {
    return make_float2(a.x * b.x - a.y * b.y, a.x * b.y + a.y * b.x);
}
__device__ __forceinline__ float2 cmulc(float2 a, float2 b) {
    return make_float2(a.x * b.x + a.y * b.y, a.y * b.x - a.x * b.y);
}

/* ============ split convert: fp32 -> fp16 hi + fp16 lo (vectorized) ======= */
__device__ __forceinline__ void split_body(const float* src, __half* h,
                                           __half* l, int i)
{
    float4 v = ((const float4*)src)[i];
    __half h0, h1, h2, h3, l0, l1, l2, l3;
    splitwh(v.x, h0, l0); splitwh(v.y, h1, l1);
    splitwh(v.z, h2, l2); splitwh(v.w, h3, l3);
    uint2 hv, lv;
    hv.x = (uint32_t)__half_as_ushort(h0) | ((uint32_t)__half_as_ushort(h1) << 16);
    hv.y = (uint32_t)__half_as_ushort(h2) | ((uint32_t)__half_as_ushort(h3) << 16);
    lv.x = (uint32_t)__half_as_ushort(l0) | ((uint32_t)__half_as_ushort(l1) << 16);
    lv.y = (uint32_t)__half_as_ushort(l2) | ((uint32_t)__half_as_ushort(l3) << 16);
    ((uint2*)h)[i] = hv;
    ((uint2*)l)[i] = lv;
}
__global__ void split_convert(const float* __restrict__ src,
                              __half* __restrict__ h,
                              __half* __restrict__ l, int n4)
{
    int i = blockIdx.x * blockDim.x + threadIdx.x;
    if (i < n4) split_body(src, h, l, i);
}
__global__ void split_convert_w4(
    const float* __restrict__ s0, const float* __restrict__ s1,
    const float* __restrict__ s2, const float* __restrict__ s3,
    __half* __restrict__ h0, __half* __restrict__ l0,
    __half* __restrict__ h1, __half* __restrict__ l1,
    __half* __restrict__ h2, __half* __restrict__ l2,
    __half* __restrict__ h3, __half* __restrict__ l3)
{
    int i = blockIdx.x * blockDim.x + threadIdx.x;
    int z = blockIdx.z;
    const float* s = (z == 0) ? s0 : (z == 1) ? s1 : (z == 2) ? s2 : s3;
    __half* h = (z == 0) ? h0 : (z == 1) ? h1 : (z == 2) ? h2 : h3;
    __half* l = (z == 0) ? l0 : (z == 1) ? l1 : (z == 2) ? l2 : l3;
    split_body(s, h, l, i);
}

/* ====== batched Q/K/V projection GEMM: one launch, grid.z selects W ======= */
/* z<2 (Q,K): A single fp16, 2 mma. z=2 (V): A split fp16, 3 mma.             */
__global__ void __launch_bounds__(256, 2) proj_gemm(
    const __half* __restrict__ Ahg, const __half* __restrict__ Alg,
    const __half* __restrict__ W0h, const __half* __restrict__ W0l,
    const __half* __restrict__ W1h, const __half* __restrict__ W1l,
    const __half* __restrict__ W2h, const __half* __restrict__ W2l,
    const float* __restrict__ bq, const float* __restrict__ bk,
    const float* __restrict__ bv,
    __half* __restrict__ Q16,
    __half* __restrict__ Kh16, __half* __restrict__ Kl16,
    float* __restrict__ Vo)
{
    constexpr int BM = 128, BN = 128;
    constexpr int ATB = BM * 64, BTB = BN * 64;
    constexpr int BUFS = 2 * ATB + 2 * BTB;
    constexpr int FM = 4, FN = 4;
    constexpr int NIT = 32;

    extern __shared__ char sm[];
    uint32_t smb = smem_u32(sm);

    int tid = threadIdx.x;
    int lane = tid & 31, wid = tid >> 5;
    int wrow = wid >> 2, wcol = wid & 3;
    int m0 = wrow * 64, n0 = wcol * 32;
    int gid = lane >> 2, tig = lane & 3;
    int z = blockIdx.z;

    const __half* Bhg = (z == 0) ? W0h : (z == 1) ? W1h : W2h;
    const __half* Blg = (z == 0) ? W0l : (z == 1) ? W1l : W2l;
    const float* bias = (z == 0) ? bq : (z == 1) ? bk : bv;
    bool useAl = (z == 2);

    const char* A8h = (const char*)Ahg + ((size_t)blockIdx.y * BM * 1024) * 2;
    const char* A8l = (const char*)Alg + ((size_t)blockIdx.y * BM * 1024) * 2;
    const char* B8h = (const char*)Bhg + ((size_t)blockIdx.x * BN * 1024) * 2;
    const char* B8l = (const char*)Blg + ((size_t)blockIdx.x * BN * 1024) * 2;

    auto fill = [&](int bf, int k0) {
        size_t kb = (size_t)k0 * 2;
        uint32_t base = smb + bf * BUFS;
#pragma unroll
        for (int i = tid; i < BM * 4; i += 256) {
            int r = i >> 2, ch = i & 3;
            size_t so = (size_t)r * 2048 + kb + ch * 16;
            CP16(base + swzt(r, ch), A8h + so);
            if (useAl) CP16(base + ATB + swzt(r, ch), A8l + so);
        }
#pragma unroll
        for (int i = tid; i < BN * 4; i += 256) {
            int r = i >> 2, ch = i & 3;
            size_t so = (size_t)r * 2048 + kb + ch * 16;
            CP16(base + 2 * ATB + swzt(r, ch), B8h + so);
            CP16(base + 2 * ATB + BTB + swzt(r, ch), B8l + so);
        }
    };

    float acc[FM][FN][4];
#pragma unroll
    for (int i = 0; i < FM; i++)
#pragma unroll
        for (int j = 0; j < FN; j++)
#pragma unroll
            for (int u = 0; u < 4; u++) acc[i][j][u] = 0.f;

    fill(0, 0);
    CP_COMMIT();
    fill(1, 32);
    CP_COMMIT();

    for (int it = 0; it < NIT; ++it) {
        if (it + 1 < NIT) { CP_WAIT1(); } else { CP_WAIT0(); }
        __syncthreads();
        int buf = it % 3;
        const char* pAh = sm + buf * BUFS;
        const char* pAl = pAh + ATB;
        const char* pBh = pAh + 2 * ATB;
        const char* pBl = pBh + BTB;
#pragma unroll
        for (int ks = 0; ks < 2; ks++) {
            uint32_t bhf[FN][2], blf[FN][2];
#pragma unroll
            for (int fn = 0; fn < FN; fn++) {
                int br = n0 + fn * 8 + gid;
                int o0 = swzt(br, ks * 2) + tig * 4;
                int o1 = swzt(br, ks * 2 + 1) + tig * 4;
                bhf[fn][0] = *(const uint32_t*)(pBh + o0);
                bhf[fn][1] = *(const uint32_t*)(pBh + o1);
                blf[fn][0] = *(const uint32_t*)(pBl + o0);
                blf[fn][1] = *(const uint32_t*)(pBl + o1);
            }
#pragma unroll
            for (int fm = 0; fm < FM; fm++) {
                int ar0 = m0 + fm * 16 + gid, ar8 = ar0 + 8;
                int o00 = swzt(ar0, ks * 2) + tig * 4;
                int o80 = swzt(ar8, ks * 2) + tig * 4;
                int o01 = swzt(ar0, ks * 2 + 1) + tig * 4;
                int o81 = swzt(ar8, ks * 2 + 1) + tig * 4;
                uint32_t ahf[4];
                ahf[0] = *(const uint32_t*)(pAh + o00);
                ahf[1] = *(const uint32_t*)(pAh + o80);
                ahf[2] = *(const uint32_t*)(pAh + o01);
                ahf[3] = *(const uint32_t*)(pAh + o81);
                if (useAl) {
                    uint32_t alf[4];
                    alf[0] = *(const uint32_t*)(pAl + o00);
                    alf[1] = *(const uint32_t*)(pAl + o80);
                    alf[2] = *(const uint32_t*)(pAl + o01);
                    alf[3] = *(const uint32_t*)(pAl + o81);
#pragma unroll
                    for (int fn = 0; fn < FN; fn++) {
                        mma_f16(acc[fm][fn], ahf, bhf[fn]);
                        mma_f16(acc[fm][fn], ahf, blf[fn]);
                        mma_f16(acc[fm][fn], alf, bhf[fn]);
                    }
                } else {
#pragma unroll
                    for (int fn = 0; fn < FN; fn++) {
                        mma_f16(acc[fm][fn], ahf, bhf[fn]);
                        mma_f16(acc[fm][fn], ahf, blf[fn]);
                    }
                }
            }
        }
        if (it + 2 < NIT) {
            fill((it + 2) % 3, (it + 2) * 32);
            CP_COMMIT();
        }
    }

#pragma unroll
    for (int fm = 0; fm < FM; fm++) {
        size_t r0 = (size_t)blockIdx.y * BM + m0 + fm * 16 + gid;
#pragma unroll
        for (int fn = 0; fn < FN; fn++) {
            int cgl = blockIdx.x * BN + n0 + fn * 8 + tig * 2;
            float b0 = bias[cgl], b1 = bias[cgl + 1];
            float v00 = acc[fm][fn][0] + b0;
            float v01 = acc[fm][fn][1] + b1;
            float v10 = acc[fm][fn][2] + b0;
            float v11 = acc[fm][fn][3] + b1;
            if (z == 2) {
                *(float2*)&Vo[r0 * 1024 + cgl] = make_float2(v00, v01);
                *(float2*)&Vo[(r0 + 8) * 1024 + cgl] = make_float2(v10, v11);
            } else if (z == 0) {
                __half2 p0 = __floats2half2_rn(v00, v01);
                __half2 p1 = __floats2half2_rn(v10, v11);
                *(uint32_t*)&Q16[r0 * 1024 + cgl] = *(uint32_t*)&p0;
                *(uint32_t*)&Q16[(r0 + 8) * 1024 + cgl] = *(uint32_t*)&p1;
            } else {
                __half h00, h01, h10, h11, l00, l01, l10, l11;
                splitwh(v00, h00, l00); splitwh(v01, h01, l01);
                splitwh(v10, h10, l10); splitwh(v11, h11, l11);
                uint32_t hv0 = (uint32_t)__half_as_ushort(h00) | ((uint32_t)__half_as_ushort(h01) << 16);
                uint32_t lv0 = (uint32_t)__half_as_ushort(l00) | ((uint32_t)__half_as_ushort(l01) << 16);
                uint32_t hv1 = (uint32_t)__half_as_ushort(h10) | ((uint32_t)__half_as_ushort(h11) << 16);
                uint32_t lv1 = (uint32_t)__half_as_ushort(l10) | ((uint32_t)__half_as_ushort(l11) << 16);
                *(uint32_t*)&Kh16[r0 * 1024 + cgl] = hv0;
                *(uint32_t*)&Kl16[r0 * 1024 + cgl] = lv0;
                *(uint32_t*)&Kh16[(r0 + 8) * 1024 + cgl] = hv1;
                *(uint32_t*)&Kl16[(r0 + 8) * 1024 + cgl] = lv1;
            }
        }
    }
}

/* == generic tensor-core GEMM (scores / AV / out), 3-stage pipeline ======== */
/* KIND 0: fp16 split x split (3 mma). KIND 1: single x split (2 mma).        */
/* KIND 2: single x single (1 mma).                                           */
template<int MODE, int EPI, int KIND, int BN, int WROWS, int WCOLS, int KTOT>
__global__ void __launch_bounds__(256, 2) mma_gemm(
    const __half* __restrict__ Ahg, const __half* __restrict__ Alg,
    const __half* __restrict__ Bhg, const __half* __restrict__ Blg,
    const float* __restrict__ bias, void* __restrict__ Cp, void* __restrict__ C2p,
    float oscale)
{
    constexpr int BM = 128;
    constexpr int ATB = BM * 64;
    constexpr int BTB = BN * 64;
    constexpr int ABYTES = (KIND >= 1 ? 1 : 2) * ATB;
    constexpr int NB = (KIND == 2) ? 1 : 2;
    constexpr int BUFS = ABYTES + NB * BTB;
    constexpr int WTM = BM / WROWS, WTN = BN / WCOLS;
    constexpr int FM = WTM / 16, FN = WTN / 8;
    constexpr int NIT = KTOT / 32;

    extern __shared__ char sm[];
    uint32_t smb = smem_u32(sm);

    int tid = threadIdx.x;
    int lane = tid & 31, wid = tid >> 5;
    int wrow = wid / WCOLS, wcol = wid % WCOLS;
    int m0 = wrow * WTM, n0 = wcol * WTN;
    int gid = lane >> 2, tig = lane & 3;

    size_t offA = 0, offB = 0, offC = 0, offP = 0;
    if (MODE == 1) {
        int z = blockIdx.z;
        size_t ho = (size_t)(z >> 4) * S_ * E_ + (size_t)(z & 15) * HD_;
        offA = ho; offB = ho;
        offP = (size_t)z * 512 * 1024;
    } else if (MODE == 2) {
        int z = blockIdx.z;
        offA = (size_t)z * S_ * S_;
        offB = (size_t)z * HD_ * S_;
        offC = (size_t)(z >> 4) * S_ * E_ + (size_t)(z & 15) * HD_;
    }
    const char* A8h = (const char*)Ahg + (offA + (size_t)blockIdx.y * BM * 1024) * 2;
    const char* A8l = (const char*)Alg + (offA + (size_t)blockIdx.y * BM * 1024) * 2;
    const char* B8h = (const char*)Bhg + (offB + (size_t)blockIdx.x * BN * 1024) * 2;
    const char* B8l = (const char*)Blg + (offB + (size_t)blockIdx.x * BN * 1024) * 2;

    auto fill = [&](int bf, int k0) {
        size_t kb = (size_t)k0 * 2;
        uint32_t base = smb + bf * BUFS;
#pragma unroll
        for (int i = tid; i < BM * 4; i += 256) {
            int r = i >> 2, ch = i & 3;
            size_t so = (size_t)r * 2048 + kb + ch * 16;
            CP16(base + swzt(r, ch), A8h + so);
            if (KIND == 0) CP16(base + ATB + swzt(r, ch), A8l + so);
        }
#pragma unroll
        for (int i = tid; i < BN * 4; i += 256) {
            int r = i >> 2, ch = i & 3;
            size_t so = (size_t)r * 2048 + kb + ch * 16;
            CP16(base + ABYTES + swzt(r, ch), B8h + so);
            if (KIND != 2) CP16(base + ABYTES + BTB + swzt(r, ch), B8l + so);
        }
    };

    float acc[FM][FN][4];
#pragma unroll
    for (int i = 0; i < FM; i++)
#pragma unroll
        for (int j = 0; j < FN; j++)
#pragma unroll
            for (int u = 0; u < 4; u++) acc[i][j][u] = 0.f;

    fill(0, 0);
    CP_COMMIT();
    if (NIT > 1) fill(1, 32);
    CP_COMMIT();

    for (int it = 0; it < NIT; ++it) {
        if (it + 1 < NIT) { CP_WAIT1(); } else { CP_WAIT0(); }
        __syncthreads();
        int buf = it % 3;
        const char* pAh = sm + buf * BUFS;
        const char* pAl = pAh + ATB;
        const char* pBh = pAh + ABYTES;
        const char* pBl = pBh + BTB;
#pragma unroll
        for (int ks = 0; ks < 2; ks++) {
            uint32_t bhf[FN][2], blf[FN][2];
#pragma unroll
            for (int fn = 0; fn < FN; fn++) {
                int br = n0 + fn * 8 + gid;
                int o0 = swzt(br, ks * 2) + tig * 4;
                int o1 = swzt(br, ks * 2 + 1) + tig * 4;
                bhf[fn][0] = *(const uint32_t*)(pBh + o0);
                bhf[fn][1] = *(const uint32_t*)(pBh + o1);
                if (KIND != 2) {
                    blf[fn][0] = *(const uint32_t*)(pBl + o0);
                    blf[fn][1] = *(const uint32_t*)(pBl + o1);
                }
            }
#pragma unroll
            for (int fm = 0; fm < FM; fm++) {
                int ar0 = m0 + fm * 16 + gid, ar8 = ar0 + 8;
                int o00 = swzt(ar0, ks * 2) + tig * 4;
                int o80 = swzt(ar8, ks * 2) + tig * 4;
                int o01 = swzt(ar0, ks * 2 + 1) + tig * 4;
                int o81 = swzt(ar8, ks * 2 + 1) + tig * 4;
                uint32_t ahf[4];
                ahf[0] = *(const uint32_t*)(pAh + o00);
                ahf[1] = *(const uint32_t*)(pAh + o80);
                ahf[2] = *(const uint32_t*)(pAh + o01);
                ahf[3] = *(const uint32_t*)(pAh + o81);
                if (KIND == 0) {
                    uint32_t alf[4];
                    alf[0] = *(const uint32_t*)(pAl + o00);
                    alf[1] = *(const uint32_t*)(pAl + o80);
                    alf[2] = *(const uint32_t*)(pAl + o01);
                    alf[3] = *(const uint32_t*)(pAl + o81);
#pragma unroll
                    for (int fn = 0; fn < FN; fn++) {
                        mma_f16(acc[fm][fn], ahf, bhf[fn]);
                        mma_f16(acc[fm][fn], ahf, blf[fn]);
                        mma_f16(acc[fm][fn], alf, bhf[fn]);
                    }
                } else if (KIND == 1) {
#pragma unroll
                    for (int fn = 0; fn < FN; fn++) {
                        mma_f16(acc[fm][fn], ahf, bhf[fn]);
                        mma_f16(acc[fm][fn], ahf, blf[fn]);
                    }
                } else {
#pragma unroll
                    for (int fn = 0; fn < FN; fn++)
                        mma_f16(acc[fm][fn], ahf, bhf[fn]);
                }
            }
        }
        if (it + 2 < NIT) {
            fill((it + 2) % 3, (it + 2) * 32);
            CP_COMMIT();
        }
    }

#pragma unroll
    for (int fm = 0; fm < FM; fm++) {
        size_t r0 = (size_t)blockIdx.y * BM + m0 + fm * 16 + gid;
#pragma unroll
        for (int fn = 0; fn < FN; fn++) {
            int cgl = blockIdx.x * BN + n0 + fn * 8 + tig * 2;
            float v00 = acc[fm][fn][0] * oscale;
            float v01 = acc[fm][fn][1] * oscale;
            float v10 = acc[fm][fn][2] * oscale;
            float v11 = acc[fm][fn][3] * oscale;
            if (EPI == 4) {
                float q00 = __shfl_xor_sync(0xffffffffu, v00, 4);
                float q01 = __shfl_xor_sync(0xffffffffu, v01, 4);
                float q10 = __shfl_xor_sync(0xffffffffu, v10, 4);
                float q11 = __shfl_xor_sync(0xffffffffu, v11, 4);
                if (!(gid & 1)) {
                    __half2* SC = (__half2*)Cp;
                    __half2 a0 = __floats2half2_rn(v00, q00);
                    __half2 a1 = __floats2half2_rn(v01, q01);
                    __half2 b0 = __floats2half2_rn(v10, q10);
                    __half2 b1 = __floats2half2_rn(v11, q11);
                    uint2 pk0 = make_uint2(*(uint32_t*)&a0, *(uint32_t*)&a1);
                    uint2 pk1 = make_uint2(*(uint32_t*)&b0, *(uint32_t*)&b1);
                    *(uint2*)&SC[offP + (r0 >> 1) * 1024 + cgl] = pk0;
                    *(uint2*)&SC[offP + ((r0 + 8) >> 1) * 1024 + cgl] = pk1;
                }
            } else if (EPI == 0) {
                float b0 = bias[cgl], b1 = bias[cgl + 1];
                float* C = (float*)Cp;
                *(float2*)&C[offC + r0 * 1024 + cgl] = make_float2(v00 + b0, v01 + b1);
                *(float2*)&C[offC + (r0 + 8) * 1024 + cgl] = make_float2(v10 + b0, v11 + b1);
            } else {
                __half* Ch = (__half*)Cp;
                __half* Cl = (__half*)C2p;
                __half h00, h01, h10, h11, l00, l01, l10, l11;
                splitwh(v00, h00, l00); splitwh(v01, h01, l01);
                splitwh(v10, h10, l10); splitwh(v11, h11, l11);
                uint32_t hv0 = (uint32_t)__half_as_ushort(h00) | ((uint32_t)__half_as_ushort(h01) << 16);
                uint32_t lv0 = (uint32_t)__half_as_ushort(l00) | ((uint32_t)__half_as_ushort(l01) << 16);
                uint32_t hv1 = (uint32_t)__half_as_ushort(h10) | ((uint32_t)__half_as_ushort(h11) << 16);
                uint32_t lv1 = (uint32_t)__half_as_ushort(l10) | ((uint32_t)__half_as_ushort(l11) << 16);
                *(uint32_t*)&Ch[offC + r0 * 1024 + cgl] = hv0;
                *(uint32_t*)&Cl[offC + r0 * 1024 + cgl] = lv0;
                *(uint32_t*)&Ch[offC + (r0 + 8) * 1024 + cgl] = hv1;
                *(uint32_t*)&Cl[offC + (r0 + 8) * 1024 + cgl] = lv1;
            }
        }
    }
}

/* ===== Vt[z][d][k] = V[b][k][h*64+d], written single fp16 ================= */
__global__ void transpose_v(const float* __restrict__ V, __half* __restrict__ Vt)
{
    __shared__ float tile[32][33];
    int z = blockIdx.z;
    int b = z >> 4, h = z & 15;
    int k0 = blockIdx.x * 32, d0 = blockIdx.y * 32;
    int tx = threadIdx.x, ty = threadIdx.y;
#pragma unroll
    for (int i = 0; i < 4; i++)
        tile[ty + i * 8][tx] =
            V[((size_t)b * S_ + k0 + ty + i * 8) * E_ + h * HD_ + d0 + tx];
    __syncthreads();
#pragma unroll
    for (int i = 0; i < 4; i++) {
        size_t o = ((size_t)z * HD_ + d0 + ty + i * 8) * S_ + k0 + tx;
        Vt[o] = __float2half(tile[tx][ty + i * 8]);
    }
}

/* ===================== twiddle init ======================================= */
__global__ void init_twiddles(float2* tw)
{
    int j = blockIdx.x * blockDim.x + threadIdx.x;
    if (j < 1024) {
        float ang = -6.28318530717958647692f * (float)j / 1024.0f;
        tw[j] = make_float2(cosf(ang), sinf(ang));
    }
}

/* ============== in-register 32-pt FFT (DIF, natural order out) ============ */
template<bool INV>
__device__ __forceinline__ void fft32r(float2* v)
{
    const float C[16] = {
        1.f, 0.980785280403230f, 0.923879532511287f, 0.831469612302545f,
        0.707106781186548f, 0.555570233019602f, 0.382683432365090f, 0.195090322016128f,
        0.f, -0.195090322016128f, -0.382683432365090f, -0.555570233019602f,
        -0.707106781186548f, -0.831469612302545f, -0.923879532511287f, -0.980785280403230f };
    const float Sn[16] = {
        0.f, 0.195090322016128f, 0.382683432365090f, 0.555570233019602f,
        0.707106781186548f, 0.831469612302545f, 0.923879532511287f, 0.980785280403230f,
        1.f, 0.980785280403230f, 0.923879532511287f, 0.831469612302545f,
        0.707106781186548f, 0.555570233019602f, 0.382683432365090f, 0.195090322016128f };
#pragma unroll
    for (int h = 16; h >= 1; h >>= 1) {
#pragma unroll
        for (int b = 0; b < 32; b += 2 * h) {
#pragma unroll
            for (int j = 0; j < h; j++) {
                int e = j * (16 / h);
                float tc = C[e];
                float ts = INV ? Sn[e] : -Sn[e];
                float2 a = v[b + j], bb = v[b + j + h];
                v[b + j] = make_float2(a.x + bb.x, a.y + bb.y);
                float dx = a.x - bb.x, dy = a.y - bb.y;
                v[b + j + h] = make_float2(dx * tc - dy * ts, dx * ts + dy * tc);
            }
        }
    }
#pragma unroll
    for (int i = 0; i < 32; i++) {
        int r = ((i & 1) << 4) | ((i & 2) << 2) | (i & 4) | ((i & 8) >> 2) | ((i & 16) >> 4);
        if (r > i) { float2 tmp = v[i]; v[i] = v[r]; v[r] = tmp; }
    }
}

/* ====== pass 1: warp fwd FFT of packed fp16 row pairs -> half spectra ===== */
__global__ void __launch_bounds__(128) fft_rows_fwd_w(
    const __half2* __restrict__ sc, __half2* __restrict__ Y,
    const float2* __restrict__ twg)
{
    __shared__ __align__(16) float pat[4 * 2112];
    int t = threadIdx.x & 31, w = threadIdx.x >> 5;
    float* pre = pat + w * 2112;
    float* pim = pre + 1056;
    size_t p = (size_t)blockIdx.x * 4 + w;
    const __half2* r01 = sc + p * 1024;

    float2 v[32];
#pragma unroll
    for (int i2 = 0; i2 < 32; i2++)
        v[i2] = __half22float2(r01[t + 32 * i2]);
    fft32r<false>(v);
#pragma unroll
    for (int k2 = 1; k2 < 32; k2++)
        v[k2] = cmul(v[k2], twg[(t * k2) & 1023]);
#pragma unroll
    for (int k2 = 0; k2 < 32; k2++) {
        pre[t * 33 + k2] = v[k2].x;
        pim[t * 33 + k2] = v[k2].y;
    }
    __syncwarp();
#pragma unroll
    for (int i1 = 0; i1 < 32; i1++)
        v[i1] = make_float2(pre[i1 * 33 + t], pim[i1 * 33 + t]);
    __syncwarp();
    fft32r<false>(v);
#pragma unroll
    for (int k1 = 0; k1 < 32; k1++) {
        pre[k1 * 33 + t] = v[k1].x;
        pim[k1 * 33 + t] = v[k1].y;
    }
    __syncwarp();

    __half2* y0 = Y + (size_t)(2 * p) * KP;
    __half2* y1 = y0 + KP;
#pragma unroll
    for (int u = 0; u <= 16; u++) {
        int k = t + 32 * u;
        if (u < 16 || t == 0) {
            int idx = u * 33 + t;
            float2 Xk = make_float2(pre[idx], pim[idx]);
            int m = (1024 - k) & 1023;
            int midx = (m >> 5) * 33 + (m & 31);
            float2 Xm = make_float2(pre[midx], pim[midx]);
            y0[k] = __floats2half2_rn(0.5f * (Xk.x + Xm.x), 0.5f * (Xk.y - Xm.y));
            y1[k] = __floats2half2_rn(0.5f * (Xk.y + Xm.y), 0.5f * (Xm.x - Xk.x));
        }
    }
}

/* ===== pass 2: warp-level col FFT + real cos-filter + col IFFT =========== */
__global__ void __launch_bounds__(128) fft_cols_w(
    __half2* __restrict__ Y, const float* __restrict__ alpha_p,
    const float2* __restrict__ twg)
{
    __shared__ __align__(16) float sm[10240];   /* slab 2x5120 / patches 4x2112 */
    float* slab_re = sm;
    float* slab_im = sm + 5120;
    int tid = threadIdx.x;
    int t = tid & 31, w = tid >> 5;
    int z = blockIdx.y;
    int kbase = blockIdx.x * 4;
    __half2* base = Y + (size_t)z * S_ * KP + kbase;

#pragma unroll 8
    for (int idx = tid; idx < 4096; idx += 128) {
        int q = idx >> 2, c = idx & 3;
        float2 val = __half22float2(base[(size_t)q * KP + c]);
        slab_re[q * 5 + c] = val.x;
        slab_im[q * 5 + c] = val.y;
    }
    __syncthreads();

    float2 v[32];
#pragma unroll
    for (int i2 = 0; i2 < 32; i2++) {
        int q = t + 32 * i2;
        v[i2] = make_float2(slab_re[q * 5 + w], slab_im[q * 5 + w]);
    }
    __syncthreads();
    float* pre = sm + w * 2112;
    float* pim = pre + 1056;

    fft32r<false>(v);
#pragma unroll
    for (int k2 = 1; k2 < 32; k2++)
        v[k2] = cmul(v[k2], twg[(t * k2) & 1023]);
#pragma unroll
    for (int k2 = 0; k2 < 32; k2++) {
        pre[t * 33 + k2] = v[k2].x;
        pim[t * 33 + k2] = v[k2].y;
    }
    __syncwarp();
#pragma unroll
    for (int i1 = 0; i1 < 32; i1++)
        v[i1] = make_float2(pre[i1 * 33 + t], pim[i1 * 33 + t]);
    __syncwarp();
    fft32r<false>(v);

    float alpha = *alpha_p;
#pragma unroll
    for (int k1 = 0; k1 < 32; k1++) {
        float mag = sqrtf(v[k1].x * v[k1].x + v[k1].y * v[k1].y);
        float g = __cosf(alpha * atanf(__logf(mag + 1e-10f)));
        v[k1].x *= g; v[k1].y *= g;
    }

    fft32r<true>(v);
#pragma unroll
    for (int i1 = 1; i1 < 32; i1++)
        v[i1] = cmulc(v[i1], twg[(t * i1) & 1023]);
#pragma unroll
    for (int i1 = 0; i1 < 32; i1++) {
        pre[t * 33 + i1] = v[i1].x;
        pim[t * 33 + i1] = v[i1].y;
    }
    __syncwarp();
#pragma unroll
    for (int k2 = 0; k2 < 32; k2++)
        v[k2] = make_float2(pre[k2 * 33 + t], pim[k2 * 33 + t]);
    __syncwarp();
    fft32r<true>(v);

    __syncthreads();
    const float scl = 1.0f / 1024.0f;
#pragma unroll
    for (int i2 = 0; i2 < 32; i2++) {
        int q = t + 32 * i2;
        slab_re[q * 5 + w] = v[i2].x * scl;
        slab_im[q * 5 + w] = v[i2].y * scl;
    }
    __syncthreads();
#pragma unroll 8
    for (int idx = tid; idx < 4096; idx += 128) {
        int q = idx >> 2, c = idx & 3;
        if (kbase + c < 513)
            base[(size_t)q * KP + c] =
                __floats2half2_rn(slab_re[q * 5 + c], slab_im[q * 5 + c]);
    }
}

/* == pass 3: warp c2r inverse + warp softmax, attn fp16 vectorized out ===== */
__global__ void __launch_bounds__(128) fft_rows_inv_softmax_w(
    const __half2* __restrict__ Y, __half* __restrict__ out16,
    const float2* __restrict__ twg)
{
    __shared__ __align__(16) float pat[4 * 2112];
    int t = threadIdx.x & 31, w = threadIdx.x >> 5;
    float* pre = pat + w * 2112;
    float* pim = pre + 1056;
    size_t p = (size_t)blockIdx.x * 4 + w;
    const __half2* y0 = Y + (size_t)(2 * p) * KP;
    const __half2* y1 = y0 + KP;

#pragma unroll
    for (int u = 0; u <= 16; u++) {
        int k = t + 32 * u;
        if (u < 16 || t == 0) {
            float2 h0 = __half22float2(y0[k]);
            float2 h1 = __half22float2(y1[k]);
            int idx = u * 33 + t;
            pre[idx] = h0.x - h1.y;
            pim[idx] = h0.y + h1.x;
            if (k >= 1 && k < 512) {
                int m = 1024 - k;
                int midx = (m >> 5) * 33 + (m & 31);
                pre[midx] = h0.x + h1.y;
                pim[midx] = h1.x - h0.y;
            }
        }
    }
    __syncwarp();
    float2 v[32];
#pragma unroll
    for (int k1 = 0; k1 < 32; k1++)
        v[k1] = make_float2(pre[k1 * 33 + t], pim[k1 * 33 + t]);
    __syncwarp();
    fft32r<true>(v);
#pragma unroll
    for (int i1 = 1; i1 < 32; i1++)
        v[i1] = cmulc(v[i1], twg[(t * i1) & 1023]);
#pragma unroll
    for (int i1 = 0; i1 < 32; i1++) {
        pre[t * 33 + i1] = v[i1].x;
        pim[t * 33 + i1] = v[i1].y;
    }
    __syncwarp();
#pragma unroll
    for (int k2 = 0; k2 < 32; k2++)
        v[k2] = make_float2(pre[k2 * 33 + t], pim[k2 * 33 + t]);
    __syncwarp();
    fft32r<true>(v);

    const float scl = 1.0f / 1024.0f;
    float m0 = -1e30f, m1 = -1e30f;
#pragma unroll
    for (int i2 = 0; i2 < 32; i2++) {
        v[i2].x *= scl; v[i2].y *= scl;
        m0 = fmaxf(m0, v[i2].x); m1 = fmaxf(m1, v[i2].y);
    }
#pragma unroll
    for (int o = 16; o; o >>= 1) {
        m0 = fmaxf(m0, __shfl_xor_sync(0xffffffffu, m0, o));
        m1 = fmaxf(m1, __shfl_xor_sync(0xffffffffu, m1, o));
    }
    float s0 = 0.f, s1 = 0.f;
    float p0[32], p1[32];
#pragma unroll
    for (int i2 = 0; i2 < 32; i2++) {
        p0[i2] = __expf(v[i2].x - m0);
        p1[i2] = __expf(v[i2].y - m1);
        s0 += p0[i2]; s1 += p1[i2];
    }
#pragma unroll
    for (int o = 16; o; o >>= 1) {
        s0 += __shfl_xor_sync(0xffffffffu, s0, o);
        s1 += __shfl_xor_sync(0xffffffffu, s1, o);
    }
    float inv0 = 1.0f / s0, inv1 = 1.0f / s1;
    __syncwarp();
    __half* hb = (__half*)pre;
#pragma unroll
    for (int i2 = 0; i2 < 32; i2++) {
        int col = t + 32 * i2;
        hb[col] = __float2half(p0[i2] * inv0);
        hb[1024 + col] = __float2half(p1[i2] * inv1);
    }
    __syncwarp();
    uint4* dst = (uint4*)(out16 + (size_t)(2 * p) * 1024);
    const uint4* srcv = (const uint4*)hb;
#pragma unroll
    for (int j = t; j < 256; j += 32) dst[j] = srcv[j];
}

/* ============================== launcher =================================== */
extern "C" void kernel_launch(void* const* d_in, const int* in_sizes, int n_in,
                              void* d_out, int out_size)
{
    const float* query = (const float*)d_in[0];
    const float* Wq    = (const float*)d_in[1];
    const float* bq    = (const float*)d_in[2];
    const float* Wk    = (const float*)d_in[3];
    const float* bk    = (const float*)d_in[4];
    const float* Wv    = (const float*)d_in[5];
    const float* bv    = (const float*)d_in[6];
    const float* Wo    = (const float*)d_in[7];
    const float* bo    = (const float*)d_in[8];
    const float* alpha = (const float*)d_in[9];
    float* out = (float*)d_out;

    __half *pqh, *pql, *pWqh, *pWql, *pWkh, *pWkl, *pWvh, *pWvl, *pWoh, *pWol;
    __half *pch, *pcl, *pQ16, *pKh16, *pKl16, *pVt16, *pA16;
    __half2 *pSc16, *pFreq;
    float *pV;
    float2 *pTw;
    cudaGetSymbolAddress((void**)&pqh, g_qh);   cudaGetSymbolAddress((void**)&pql, g_ql);
    cudaGetSymbolAddress((void**)&pWqh, g_Wqh); cudaGetSymbolAddress((void**)&pWql, g_Wql);
    cudaGetSymbolAddress((void**)&pWkh, g_Wkh); cudaGetSymbolAddress((void**)&pWkl, g_Wkl);
    cudaGetSymbolAddress((void**)&pWvh, g_Wvh); cudaGetSymbolAddress((void**)&pWvl, g_Wvl);
    cudaGetSymbolAddress((void**)&pWoh, g_Woh); cudaGetSymbolAddress((void**)&pWol, g_Wol);
    cudaGetSymbolAddress((void**)&pQ16, g_Q16);
    cudaGetSymbolAddress((void**)&pKh16, g_Kh16);
    cudaGetSymbolAddress((void**)&pKl16, g_Kl16);
    cudaGetSymbolAddress((void**)&pVt16, g_Vt16);
    cudaGetSymbolAddress((void**)&pch, g_ch);   cudaGetSymbolAddress((void**)&pcl, g_cl);
    cudaGetSymbolAddress((void**)&pV, g_V);
    cudaGetSymbolAddress((void**)&pSc16, g_sc16);
    cudaGetSymbolAddress((void**)&pA16, g_a16);
    cudaGetSymbolAddress((void**)&pFreq, g_freq);
    cudaGetSymbolAddress((void**)&pTw, g_tw);

    const int SM_P = 3 * (2 * 8192 + 2 * 8192);   /* 98304 */
    const int SM_S = 3 * (1 * 8192 + 2 * 8192);   /* 73728 */
    const int SM_A = 3 * (1 * 8192 + 1 * 4096);   /* 36864 */
    cudaFuncSetAttribute((const void*)proj_gemm,
                         cudaFuncAttributeMaxDynamicSharedMemorySize, SM_P);
    cudaFuncSetAttribute((const void*)mma_gemm<0, 0, 0, 128, 2, 4, 1024>,
                         cudaFuncAttributeMaxDynamicSharedMemorySize, SM_P);
    cudaFuncSetAttribute((const void*)mma_gemm<1, 4, 1, 128, 2, 4, 64>,
                         cudaFuncAttributeMaxDynamicSharedMemorySize, SM_S);
    cudaFuncSetAttribute((const void*)mma_gemm<2, 3, 2, 64, 4, 2, 1024>,
                         cudaFuncAttributeMaxDynamicSharedMemorySize, SM_A);

    init_twiddles<<<4, 256>>>(pTw);

    split_convert<<<(int)(NELEM / 4 / 256), 256>>>(query, pqh, pql, (int)(NELEM / 4));
    split_convert_w4<<<dim3(E_ * E_ / 4 / 256, 1, 4), 256>>>(
        Wq, Wk, Wv, Wo, pWqh, pWql, pWkh, pWkl, pWvh, pWvl, pWoh, pWol);

    dim3 gp3(E_ / 128, (B_ * S_) / 128, 3);
    proj_gemm<<<gp3, 256, SM_P>>>(pqh, pql,
                                  pWqh, pWql, pWkh, pWkl, pWvh, pWvl,
                                  bq, bk, bv,
                                  pQ16, pKh16, pKl16, pV);

    transpose_v<<<dim3(32, 2, NBH), dim3(32, 8)>>>(pV, pVt16);

    dim3 gs(S_ / 128, S_ / 128, NBH);
    mma_gemm<1, 4, 1, 128, 2, 4, 64><<<gs, 256, SM_S>>>(
        pQ16, 0, pKh16, pKl16, 0, pSc16, 0, 0.125f);

    fft_rows_fwd_w<<<NBH * S_ / 2 / 4, 128>>>(pSc16, pFreq, pTw);

    fft_cols_w<<<dim3(129, NBH), 128>>>(pFreq, alpha, pTw);

    fft_rows_inv_softmax_w<<<NBH * S_ / 2 / 4, 128>>>(pFreq, pA16, pTw);

    dim3 ga(1, S_ / 128, NBH);
    mma_gemm<2, 3, 2, 64, 4, 2, 1024><<<ga, 256, SM_A>>>(
        pA16, 0, pVt16, 0, 0, pch, pcl, 1.0f);

    dim3 gp(E_ / 128, (B_ * S_) / 128, 1);
    mma_gemm<0, 0, 0, 128, 2, 4, 1024><<<gp, 256, SM_P>>>(pch, pcl, pWoh, pWol, bo, out, 0, 1.0f);
}

// round 16
// speedup vs baseline: 1.1112x; 1.0468x over previous
#include <cuda_runtime.h>
#include <cuda_fp16.h>
#include <math.h>
#include <stdint.h>

#define B_   4
#define S_   1024
#define E_   1024
#define H_   16
#define HD_  64
#define NBH  64          /* B*H */
#define KP   528         /* padded half-spectrum width */
#define NELEM ((size_t)B_ * S_ * E_)   /* 4M */

/* ---------------- scratch (device globals: no allocations allowed) -------- */
__device__ __half g_qh[NELEM],  g_ql[NELEM];          /* query fp16 split   */
__device__ __half g_Wqh[E_*E_], g_Wql[E_*E_];
__device__ __half g_Wkh[E_*E_], g_Wkl[E_*E_];
__device__ __half g_Wvh[E_*E_], g_Wvl[E_*E_];
__device__ __half g_Woh[E_*E_], g_Wol[E_*E_];
__device__ __half g_Q16[NELEM];                       /* Q single fp16      */
__device__ __half g_K16[NELEM];                       /* K single fp16      */
__device__ float  g_V[NELEM];
__device__ __half g_Vt16[NELEM];                      /* V^T single fp16    */
__device__ __half2 g_sc16[(size_t)NBH * 512 * 1024];  /* row-pair scores    */
__device__ __half g_a16[(size_t)NBH * S_ * S_];       /* attn fp16          */
__device__ __half g_c16[NELEM];                       /* ctx single fp16    */
__device__ __half2 g_freq[(size_t)NBH * S_ * KP];
__device__ float2 g_tw[1024];

/* ======================= small helpers ==================================== */
__device__ __forceinline__ uint32_t smem_u32(const void* p) {
    uint32_t a;
    asm("{ .reg .u64 t; cvta.to.shared.u64 t, %1; cvt.u32.u64 %0, t; }"
        : "=r"(a) : "l"(p));
    return a;
}
#define CP16(dst, src) \
    asm volatile("cp.async.cg.shared.global [%0], [%1], 16;" \
                 :: "r"(dst), "l"(src))
#define CP_COMMIT() asm volatile("cp.async.commit_group;" ::: "memory")
#define CP_WAIT1()  asm volatile("cp.async.wait_group 1;" ::: "memory")
#define CP_WAIT0()  asm volatile("cp.async.wait_group 0;" ::: "memory")

__device__ __forceinline__ void mma_f16(float* d, const uint32_t* a, const uint32_t* b)
{
    asm volatile(
        "mma.sync.aligned.m16n8k16.row.col.f32.f16.f16.f32 "
        "{%0,%1,%2,%3}, {%4,%5,%6,%7}, {%8,%9}, {%0,%1,%2,%3};"
        : "+f"(d[0]), "+f"(d[1]), "+f"(d[2]), "+f"(d[3])
        : "r"(a[0]), "r"(a[1]), "r"(a[2]), "r"(a[3]), "r"(b[0]), "r"(b[1]));
}

__device__ __forceinline__ int swzt(int row, int ch) {
    return (row << 6) + ((ch ^ ((row >> 1) & 3)) << 4);
}

__device__ __forceinline__ void splitwh(float v, __half& h, __half& l) {
    h = __float2half(v);
    l = __float2half(v - __half2float(h));
}

__device__ __forceinline__ float2 cmul(float2 a, float2 b) {
    return make_float2(a.x * b.x - a.y * b.y, a.x * b.y + a.y * b.x);
}
__device__ __forceinline__ float2 cmulc(float2 a, float2 b) {
    return make_float2(a.x * b.x + a.y * b.y, a.y * b.x - a.x * b.y);
}

/* ============ split convert: fp32 -> fp16 hi + fp16 lo (vectorized) ======= */
__device__ __forceinline__ void split_body(const float* src, __half* h,
                                           __half* l, int i)
{
    float4 v = ((const float4*)src)[i];
    __half h0, h1, h2, h3, l0, l1, l2, l3;
    splitwh(v.x, h0, l0); splitwh(v.y, h1, l1);
    splitwh(v.z, h2, l2); splitwh(v.w, h3, l3);
    uint2 hv, lv;
    hv.x = (uint32_t)__half_as_ushort(h0) | ((uint32_t)__half_as_ushort(h1) << 16);
    hv.y = (uint32_t)__half_as_ushort(h2) | ((uint32_t)__half_as_ushort(h3) << 16);
    lv.x = (uint32_t)__half_as_ushort(l0) | ((uint32_t)__half_as_ushort(l1) << 16);
    lv.y = (uint32_t)__half_as_ushort(l2) | ((uint32_t)__half_as_ushort(l3) << 16);
    ((uint2*)h)[i] = hv;
    ((uint2*)l)[i] = lv;
}
__global__ void split_convert(const float* __restrict__ src,
                              __half* __restrict__ h,
                              __half* __restrict__ l, int n4)
{
    int i = blockIdx.x * blockDim.x + threadIdx.x;
    if (i < n4) split_body(src, h, l, i);
}
__global__ void split_convert_w4(
    const float* __restrict__ s0, const float* __restrict__ s1,
    const float* __restrict__ s2, const float* __restrict__ s3,
    __half* __restrict__ h0, __half* __restrict__ l0,
    __half* __restrict__ h1, __half* __restrict__ l1,
    __half* __restrict__ h2, __half* __restrict__ l2,
    __half* __restrict__ h3, __half* __restrict__ l3)
{
    int i = blockIdx.x * blockDim.x + threadIdx.x;
    int z = blockIdx.z;
    const float* s = (z == 0) ? s0 : (z == 1) ? s1 : (z == 2) ? s2 : s3;
    __half* h = (z == 0) ? h0 : (z == 1) ? h1 : (z == 2) ? h2 : h3;
    __half* l = (z == 0) ? l0 : (z == 1) ? l1 : (z == 2) ? l2 : l3;
    split_body(s, h, l, i);
}

/* ====== batched Q/K/V projection GEMM: one launch, grid.z selects W ======= */
/* z<2 (Q,K): A single fp16, 2 mma, single out. z=2 (V): 3 mma, fp32 out.     */
__global__ void __launch_bounds__(256, 2) proj_gemm(
    const __half* __restrict__ Ahg, const __half* __restrict__ Alg,
    const __half* __restrict__ W0h, const __half* __restrict__ W0l,
    const __half* __restrict__ W1h, const __half* __restrict__ W1l,
    const __half* __restrict__ W2h, const __half* __restrict__ W2l,
    const float* __restrict__ bq, const float* __restrict__ bk,
    const float* __restrict__ bv,
    __half* __restrict__ Q16, __half* __restrict__ K16,
    float* __restrict__ Vo)
{
    constexpr int BM = 128, BN = 128;
    constexpr int ATB = BM * 64, BTB = BN * 64;
    constexpr int BUFS = 2 * ATB + 2 * BTB;
    constexpr int FM = 4, FN = 4;
    constexpr int NIT = 32;

    extern __shared__ char sm[];
    uint32_t smb = smem_u32(sm);

    int tid = threadIdx.x;
    int lane = tid & 31, wid = tid >> 5;
    int wrow = wid >> 2, wcol = wid & 3;
    int m0 = wrow * 64, n0 = wcol * 32;
    int gid = lane >> 2, tig = lane & 3;
    int z = blockIdx.z;

    const __half* Bhg = (z == 0) ? W0h : (z == 1) ? W1h : W2h;
    const __half* Blg = (z == 0) ? W0l : (z == 1) ? W1l : W2l;
    const float* bias = (z == 0) ? bq : (z == 1) ? bk : bv;
    bool useAl = (z == 2);

    const char* A8h = (const char*)Ahg + ((size_t)blockIdx.y * BM * 1024) * 2;
    const char* A8l = (const char*)Alg + ((size_t)blockIdx.y * BM * 1024) * 2;
    const char* B8h = (const char*)Bhg + ((size_t)blockIdx.x * BN * 1024) * 2;
    const char* B8l = (const char*)Blg + ((size_t)blockIdx.x * BN * 1024) * 2;

    auto fill = [&](int bf, int k0) {
        size_t kb = (size_t)k0 * 2;
        uint32_t base = smb + bf * BUFS;
#pragma unroll
        for (int i = tid; i < BM * 4; i += 256) {
            int r = i >> 2, ch = i & 3;
            size_t so = (size_t)r * 2048 + kb + ch * 16;
            CP16(base + swzt(r, ch), A8h + so);
            if (useAl) CP16(base + ATB + swzt(r, ch), A8l + so);
        }
#pragma unroll
        for (int i = tid; i < BN * 4; i += 256) {
            int r = i >> 2, ch = i & 3;
            size_t so = (size_t)r * 2048 + kb + ch * 16;
            CP16(base + 2 * ATB + swzt(r, ch), B8h + so);
            CP16(base + 2 * ATB + BTB + swzt(r, ch), B8l + so);
        }
    };

    float acc[FM][FN][4];
#pragma unroll
    for (int i = 0; i < FM; i++)
#pragma unroll
        for (int j = 0; j < FN; j++)
#pragma unroll
            for (int u = 0; u < 4; u++) acc[i][j][u] = 0.f;

    fill(0, 0);
    CP_COMMIT();
    fill(1, 32);
    CP_COMMIT();

    for (int it = 0; it < NIT; ++it) {
        if (it + 1 < NIT) { CP_WAIT1(); } else { CP_WAIT0(); }
        __syncthreads();
        int buf = it % 3;
        const char* pAh = sm + buf * BUFS;
        const char* pAl = pAh + ATB;
        const char* pBh = pAh + 2 * ATB;
        const char* pBl = pBh + BTB;
#pragma unroll
        for (int ks = 0; ks < 2; ks++) {
            uint32_t bhf[FN][2], blf[FN][2];
#pragma unroll
            for (int fn = 0; fn < FN; fn++) {
                int br = n0 + fn * 8 + gid;
                int o0 = swzt(br, ks * 2) + tig * 4;
                int o1 = swzt(br, ks * 2 + 1) + tig * 4;
                bhf[fn][0] = *(const uint32_t*)(pBh + o0);
                bhf[fn][1] = *(const uint32_t*)(pBh + o1);
                blf[fn][0] = *(const uint32_t*)(pBl + o0);
                blf[fn][1] = *(const uint32_t*)(pBl + o1);
            }
#pragma unroll
            for (int fm = 0; fm < FM; fm++) {
                int ar0 = m0 + fm * 16 + gid, ar8 = ar0 + 8;
                int o00 = swzt(ar0, ks * 2) + tig * 4;
                int o80 = swzt(ar8, ks * 2) + tig * 4;
                int o01 = swzt(ar0, ks * 2 + 1) + tig * 4;
                int o81 = swzt(ar8, ks * 2 + 1) + tig * 4;
                uint32_t ahf[4];
                ahf[0] = *(const uint32_t*)(pAh + o00);
                ahf[1] = *(const uint32_t*)(pAh + o80);
                ahf[2] = *(const uint32_t*)(pAh + o01);
                ahf[3] = *(const uint32_t*)(pAh + o81);
                if (useAl) {
                    uint32_t alf[4];
                    alf[0] = *(const uint32_t*)(pAl + o00);
                    alf[1] = *(const uint32_t*)(pAl + o80);
                    alf[2] = *(const uint32_t*)(pAl + o01);
                    alf[3] = *(const uint32_t*)(pAl + o81);
#pragma unroll
                    for (int fn = 0; fn < FN; fn++) {
                        mma_f16(acc[fm][fn], ahf, bhf[fn]);
                        mma_f16(acc[fm][fn], ahf, blf[fn]);
                        mma_f16(acc[fm][fn], alf, bhf[fn]);
                    }
                } else {
#pragma unroll
                    for (int fn = 0; fn < FN; fn++) {
                        mma_f16(acc[fm][fn], ahf, bhf[fn]);
                        mma_f16(acc[fm][fn], ahf, blf[fn]);
                    }
                }
            }
        }
        if (it + 2 < NIT) {
            fill((it + 2) % 3, (it + 2) * 32);
            CP_COMMIT();
        }
    }

    __half* Cout = (z == 0) ? Q16 : K16;
#pragma unroll
    for (int fm = 0; fm < FM; fm++) {
        size_t r0 = (size_t)blockIdx.y * BM + m0 + fm * 16 + gid;
#pragma unroll
        for (int fn = 0; fn < FN; fn++) {
            int cgl = blockIdx.x * BN + n0 + fn * 8 + tig * 2;
            float b0 = bias[cgl], b1 = bias[cgl + 1];
            float v00 = acc[fm][fn][0] + b0;
            float v01 = acc[fm][fn][1] + b1;
            float v10 = acc[fm][fn][2] + b0;
            float v11 = acc[fm][fn][3] + b1;
            if (z == 2) {
                *(float2*)&Vo[r0 * 1024 + cgl] = make_float2(v00, v01);
                *(float2*)&Vo[(r0 + 8) * 1024 + cgl] = make_float2(v10, v11);
            } else {
                __half2 p0 = __floats2half2_rn(v00, v01);
                __half2 p1 = __floats2half2_rn(v10, v11);
                *(uint32_t*)&Cout[r0 * 1024 + cgl] = *(uint32_t*)&p0;
                *(uint32_t*)&Cout[(r0 + 8) * 1024 + cgl] = *(uint32_t*)&p1;
            }
        }
    }
}

/* == generic tensor-core GEMM (scores / AV / out), 3-stage pipeline ======== */
/* KIND 1: A single x B split (2 mma). KIND 2: single x single (1 mma).       */
/* EPI 0: fp32+bias; 4: half2 row-pair scores; 5: single fp16.                */
template<int MODE, int EPI, int KIND, int BN, int WROWS, int WCOLS, int KTOT>
__global__ void __launch_bounds__(256, 2) mma_gemm(
    const __half* __restrict__ Ahg,
    const __half* __restrict__ Bhg, const __half* __restrict__ Blg,
    const float* __restrict__ bias, void* __restrict__ Cp,
    float oscale)
{
    constexpr int BM = 128;
    constexpr int ATB = BM * 64;
    constexpr int BTB = BN * 64;
    constexpr int NB = (KIND == 2) ? 1 : 2;
    constexpr int BUFS = ATB + NB * BTB;
    constexpr int WTM = BM / WROWS, WTN = BN / WCOLS;
    constexpr int FM = WTM / 16, FN = WTN / 8;
    constexpr int NIT = KTOT / 32;

    extern __shared__ char sm[];
    uint32_t smb = smem_u32(sm);

    int tid = threadIdx.x;
    int lane = tid & 31, wid = tid >> 5;
    int wrow = wid / WCOLS, wcol = wid % WCOLS;
    int m0 = wrow * WTM, n0 = wcol * WTN;
    int gid = lane >> 2, tig = lane & 3;

    size_t offA = 0, offB = 0, offC = 0, offP = 0;
    if (MODE == 1) {
        int z = blockIdx.z;
        size_t ho = (size_t)(z >> 4) * S_ * E_ + (size_t)(z & 15) * HD_;
        offA = ho; offB = ho;
        offP = (size_t)z * 512 * 1024;
    } else if (MODE == 2) {
        int z = blockIdx.z;
        offA = (size_t)z * S_ * S_;
        offB = (size_t)z * HD_ * S_;
        offC = (size_t)(z >> 4) * S_ * E_ + (size_t)(z & 15) * HD_;
    }
    const char* A8h = (const char*)Ahg + (offA + (size_t)blockIdx.y * BM * 1024) * 2;
    const char* B8h = (const char*)Bhg + (offB + (size_t)blockIdx.x * BN * 1024) * 2;
    const char* B8l = (const char*)Blg + (offB + (size_t)blockIdx.x * BN * 1024) * 2;

    auto fill = [&](int bf, int k0) {
        size_t kb = (size_t)k0 * 2;
        uint32_t base = smb + bf * BUFS;
#pragma unroll
        for (int i = tid; i < BM * 4; i += 256) {
            int r = i >> 2, ch = i & 3;
            size_t so = (size_t)r * 2048 + kb + ch * 16;
            CP16(base + swzt(r, ch), A8h + so);
        }
#pragma unroll
        for (int i = tid; i < BN * 4; i += 256) {
            int r = i >> 2, ch = i & 3;
            size_t so = (size_t)r * 2048 + kb + ch * 16;
            CP16(base + ATB + swzt(r, ch), B8h + so);
            if (KIND != 2) CP16(base + ATB + BTB + swzt(r, ch), B8l + so);
        }
    };

    float acc[FM][FN][4];
#pragma unroll
    for (int i = 0; i < FM; i++)
#pragma unroll
        for (int j = 0; j < FN; j++)
#pragma unroll
            for (int u = 0; u < 4; u++) acc[i][j][u] = 0.f;

    fill(0, 0);
    CP_COMMIT();
    if (NIT > 1) fill(1, 32);
    CP_COMMIT();

    for (int it = 0; it < NIT; ++it) {
        if (it + 1 < NIT) { CP_WAIT1(); } else { CP_WAIT0(); }
        __syncthreads();
        int buf = it % 3;
        const char* pAh = sm + buf * BUFS;
        const char* pBh = pAh + ATB;
        const char* pBl = pBh + BTB;
#pragma unroll
        for (int ks = 0; ks < 2; ks++) {
            uint32_t bhf[FN][2], blf[FN][2];
#pragma unroll
            for (int fn = 0; fn < FN; fn++) {
                int br = n0 + fn * 8 + gid;
                int o0 = swzt(br, ks * 2) + tig * 4;
                int o1 = swzt(br, ks * 2 + 1) + tig * 4;
                bhf[fn][0] = *(const uint32_t*)(pBh + o0);
                bhf[fn][1] = *(const uint32_t*)(pBh + o1);
                if (KIND != 2) {
                    blf[fn][0] = *(const uint32_t*)(pBl + o0);
                    blf[fn][1] = *(const uint32_t*)(pBl + o1);
                }
            }
#pragma unroll
            for (int fm = 0; fm < FM; fm++) {
                int ar0 = m0 + fm * 16 + gid, ar8 = ar0 + 8;
                uint32_t ahf[4];
                ahf[0] = *(const uint32_t*)(pAh + swzt(ar0, ks * 2) + tig * 4);
                ahf[1] = *(const uint32_t*)(pAh + swzt(ar8, ks * 2) + tig * 4);
                ahf[2] = *(const uint32_t*)(pAh + swzt(ar0, ks * 2 + 1) + tig * 4);
                ahf[3] = *(const uint32_t*)(pAh + swzt(ar8, ks * 2 + 1) + tig * 4);
                if (KIND == 1) {
#pragma unroll
                    for (int fn = 0; fn < FN; fn++) {
                        mma_f16(acc[fm][fn], ahf, bhf[fn]);
                        mma_f16(acc[fm][fn], ahf, blf[fn]);
                    }
                } else {
#pragma unroll
                    for (int fn = 0; fn < FN; fn++)
                        mma_f16(acc[fm][fn], ahf, bhf[fn]);
                }
            }
        }
        if (it + 2 < NIT) {
            fill((it + 2) % 3, (it + 2) * 32);
            CP_COMMIT();
        }
    }

#pragma unroll
    for (int fm = 0; fm < FM; fm++) {
        size_t r0 = (size_t)blockIdx.y * BM + m0 + fm * 16 + gid;
#pragma unroll
        for (int fn = 0; fn < FN; fn++) {
            int cgl = blockIdx.x * BN + n0 + fn * 8 + tig * 2;
            float v00 = acc[fm][fn][0] * oscale;
            float v01 = acc[fm][fn][1] * oscale;
            float v10 = acc[fm][fn][2] * oscale;
            float v11 = acc[fm][fn][3] * oscale;
            if (EPI == 4) {
                float q00 = __shfl_xor_sync(0xffffffffu, v00, 4);
                float q01 = __shfl_xor_sync(0xffffffffu, v01, 4);
                float q10 = __shfl_xor_sync(0xffffffffu, v10, 4);
                float q11 = __shfl_xor_sync(0xffffffffu, v11, 4);
                if (!(gid & 1)) {
                    __half2* SC = (__half2*)Cp;
                    __half2 a0 = __floats2half2_rn(v00, q00);
                    __half2 a1 = __floats2half2_rn(v01, q01);
                    __half2 b0 = __floats2half2_rn(v10, q10);
                    __half2 b1 = __floats2half2_rn(v11, q11);
                    uint2 pk0 = make_uint2(*(uint32_t*)&a0, *(uint32_t*)&a1);
                    uint2 pk1 = make_uint2(*(uint32_t*)&b0, *(uint32_t*)&b1);
                    *(uint2*)&SC[offP + (r0 >> 1) * 1024 + cgl] = pk0;
                    *(uint2*)&SC[offP + ((r0 + 8) >> 1) * 1024 + cgl] = pk1;
                }
            } else if (EPI == 0) {
                float b0 = bias[cgl], b1 = bias[cgl + 1];
                float* C = (float*)Cp;
                *(float2*)&C[offC + r0 * 1024 + cgl] = make_float2(v00 + b0, v01 + b1);
                *(float2*)&C[offC + (r0 + 8) * 1024 + cgl] = make_float2(v10 + b0, v11 + b1);
            } else {
                __half* Ch = (__half*)Cp;
                __half2 p0 = __floats2half2_rn(v00, v01);
                __half2 p1 = __floats2half2_rn(v10, v11);
                *(uint32_t*)&Ch[offC + r0 * 1024 + cgl] = *(uint32_t*)&p0;
                *(uint32_t*)&Ch[offC + (r0 + 8) * 1024 + cgl] = *(uint32_t*)&p1;
            }
        }
    }
}

/* ===== Vt[z][d][k] = V[b][k][h*64+d], written single fp16 ================= */
__global__ void transpose_v(const float* __restrict__ V, __half* __restrict__ Vt)
{
    __shared__ float tile[32][33];
    int z = blockIdx.z;
    int b = z >> 4, h = z & 15;
    int k0 = blockIdx.x * 32, d0 = blockIdx.y * 32;
    int tx = threadIdx.x, ty = threadIdx.y;
#pragma unroll
    for (int i = 0; i < 4; i++)
        tile[ty + i * 8][tx] =
            V[((size_t)b * S_ + k0 + ty + i * 8) * E_ + h * HD_ + d0 + tx];
    __syncthreads();
#pragma unroll
    for (int i = 0; i < 4; i++) {
        size_t o = ((size_t)z * HD_ + d0 + ty + i * 8) * S_ + k0 + tx;
        Vt[o] = __float2half(tile[tx][ty + i * 8]);
    }
}

/* ===================== twiddle init ======================================= */
__global__ void init_twiddles(float2* tw)
{
    int j = blockIdx.x * blockDim.x + threadIdx.x;
    if (j < 1024) {
        float ang = -6.28318530717958647692f * (float)j / 1024.0f;
        tw[j] = make_float2(cosf(ang), sinf(ang));
    }
}

/* ============== in-register 32-pt FFT (DIF, natural order out) ============ */
template<bool INV>
__device__ __forceinline__ void fft32r(float2* v)
{
    const float C[16] = {
        1.f, 0.980785280403230f, 0.923879532511287f, 0.831469612302545f,
        0.707106781186548f, 0.555570233019602f, 0.382683432365090f, 0.195090322016128f,
        0.f, -0.195090322016128f, -0.382683432365090f, -0.555570233019602f,
        -0.707106781186548f, -0.831469612302545f, -0.923879532511287f, -0.980785280403230f };
    const float Sn[16] = {
        0.f, 0.195090322016128f, 0.382683432365090f, 0.555570233019602f,
        0.707106781186548f, 0.831469612302545f, 0.923879532511287f, 0.980785280403230f,
        1.f, 0.980785280403230f, 0.923879532511287f, 0.831469612302545f,
        0.707106781186548f, 0.555570233019602f, 0.382683432365090f, 0.195090322016128f };
#pragma unroll
    for (int h = 16; h >= 1; h >>= 1) {
#pragma unroll
        for (int b = 0; b < 32; b += 2 * h) {
#pragma unroll
            for (int j = 0; j < h; j++) {
                int e = j * (16 / h);
                float tc = C[e];
                float ts = INV ? Sn[e] : -Sn[e];
                float2 a = v[b + j], bb = v[b + j + h];
                v[b + j] = make_float2(a.x + bb.x, a.y + bb.y);
                float dx = a.x - bb.x, dy = a.y - bb.y;
                v[b + j + h] = make_float2(dx * tc - dy * ts, dx * ts + dy * tc);
            }
        }
    }
#pragma unroll
    for (int i = 0; i < 32; i++) {
        int r = ((i & 1) << 4) | ((i & 2) << 2) | (i & 4) | ((i & 8) >> 2) | ((i & 16) >> 4);
        if (r > i) { float2 tmp = v[i]; v[i] = v[r]; v[r] = tmp; }
    }
}

/* ====== pass 1: warp fwd FFT of packed fp16 row pairs -> half spectra ===== */
__global__ void __launch_bounds__(128) fft_rows_fwd_w(
    const __half2* __restrict__ sc, __half2* __restrict__ Y,
    const float2* __restrict__ twg)
{
    __shared__ __align__(16) float pat[4 * 2112];
    int t = threadIdx.x & 31, w = threadIdx.x >> 5;
    float* pre = pat + w * 2112;
    float* pim = pre + 1056;
    size_t p = (size_t)blockIdx.x * 4 + w;
    const __half2* r01 = sc + p * 1024;

    float2 v[32];
#pragma unroll
    for (int i2 = 0; i2 < 32; i2++)
        v[i2] = __half22float2(r01[t + 32 * i2]);
    fft32r<false>(v);
#pragma unroll
    for (int k2 = 1; k2 < 32; k2++)
        v[k2] = cmul(v[k2], twg[(t * k2) & 1023]);
#pragma unroll
    for (int k2 = 0; k2 < 32; k2++) {
        pre[t * 33 + k2] = v[k2].x;
        pim[t * 33 + k2] = v[k2].y;
    }
    __syncwarp();
#pragma unroll
    for (int i1 = 0; i1 < 32; i1++)
        v[i1] = make_float2(pre[i1 * 33 + t], pim[i1 * 33 + t]);
    __syncwarp();
    fft32r<false>(v);
#pragma unroll
    for (int k1 = 0; k1 < 32; k1++) {
        pre[k1 * 33 + t] = v[k1].x;
        pim[k1 * 33 + t] = v[k1].y;
    }
    __syncwarp();

    __half2* y0 = Y + (size_t)(2 * p) * KP;
    __half2* y1 = y0 + KP;
#pragma unroll
    for (int u = 0; u <= 16; u++) {
        int k = t + 32 * u;
        if (u < 16 || t == 0) {
            int idx = u * 33 + t;
            float2 Xk = make_float2(pre[idx], pim[idx]);
            int m = (1024 - k) & 1023;
            int midx = (m >> 5) * 33 + (m & 31);
            float2 Xm = make_float2(pre[midx], pim[midx]);
            y0[k] = __floats2half2_rn(0.5f * (Xk.x + Xm.x), 0.5f * (Xk.y - Xm.y));
            y1[k] = __floats2half2_rn(0.5f * (Xk.y + Xm.y), 0.5f * (Xm.x - Xk.x));
        }
    }
}

/* ===== pass 2: warp-level col FFT + real cos-filter + col IFFT =========== */
__global__ void __launch_bounds__(128) fft_cols_w(
    __half2* __restrict__ Y, const float* __restrict__ alpha_p,
    const float2* __restrict__ twg)
{
    __shared__ __align__(16) float sm[10240];   /* slab 2x5120 / patches 4x2112 */
    float* slab_re = sm;
    float* slab_im = sm + 5120;
    int tid = threadIdx.x;
    int t = tid & 31, w = tid >> 5;
    int z = blockIdx.y;
    int kbase = blockIdx.x * 4;
    __half2* base = Y + (size_t)z * S_ * KP + kbase;

#pragma unroll 8
    for (int idx = tid; idx < 4096; idx += 128) {
        int q = idx >> 2, c = idx & 3;
        float2 val = __half22float2(base[(size_t)q * KP + c]);
        slab_re[q * 5 + c] = val.x;
        slab_im[q * 5 + c] = val.y;
    }
    __syncthreads();

    float2 v[32];
#pragma unroll
    for (int i2 = 0; i2 < 32; i2++) {
        int q = t + 32 * i2;
        v[i2] = make_float2(slab_re[q * 5 + w], slab_im[q * 5 + w]);
    }
    __syncthreads();
    float* pre = sm + w * 2112;
    float* pim = pre + 1056;

    fft32r<false>(v);
#pragma unroll
    for (int k2 = 1; k2 < 32; k2++)
        v[k2] = cmul(v[k2], twg[(t * k2) & 1023]);
#pragma unroll
    for (int k2 = 0; k2 < 32; k2++) {
        pre[t * 33 + k2] = v[k2].x;
        pim[t * 33 + k2] = v[k2].y;
    }
    __syncwarp();
#pragma unroll
    for (int i1 = 0; i1 < 32; i1++)
        v[i1] = make_float2(pre[i1 * 33 + t], pim[i1 * 33 + t]);
    __syncwarp();
    fft32r<false>(v);

    float alpha = *alpha_p;
#pragma unroll
    for (int k1 = 0; k1 < 32; k1++) {
        float mag = sqrtf(v[k1].x * v[k1].x + v[k1].y * v[k1].y);
        float g = __cosf(alpha * atanf(__logf(mag + 1e-10f)));
        v[k1].x *= g; v[k1].y *= g;
    }

    fft32r<true>(v);
#pragma unroll
    for (int i1 = 1; i1 < 32; i1++)
        v[i1] = cmulc(v[i1], twg[(t * i1) & 1023]);
#pragma unroll
    for (int i1 = 0; i1 < 32; i1++) {
        pre[t * 33 + i1] = v[i1].x;
        pim[t * 33 + i1] = v[i1].y;
    }
    __syncwarp();
#pragma unroll
    for (int k2 = 0; k2 < 32; k2++)
        v[k2] = make_float2(pre[k2 * 33 + t], pim[k2 * 33 + t]);
    __syncwarp();
    fft32r<true>(v);

    __syncthreads();
    const float scl = 1.0f / 1024.0f;
#pragma unroll
    for (int i2 = 0; i2 < 32; i2++) {
        int q = t + 32 * i2;
        slab_re[q * 5 + w] = v[i2].x * scl;
        slab_im[q * 5 + w] = v[i2].y * scl;
    }
    __syncthreads();
#pragma unroll 8
    for (int idx = tid; idx < 4096; idx += 128) {
        int q = idx >> 2, c = idx & 3;
        if (kbase + c < 513)
            base[(size_t)q * KP + c] =
                __floats2half2_rn(slab_re[q * 5 + c], slab_im[q * 5 + c]);
    }
}

/* == pass 3: warp c2r inverse + warp softmax, attn fp16 vectorized out ===== */
__global__ void __launch_bounds__(128) fft_rows_inv_softmax_w(
    const __half2* __restrict__ Y, __half* __restrict__ out16,
    const float2* __restrict__ twg)
{
    __shared__ __align__(16) float pat[4 * 2112];
    int t = threadIdx.x & 31, w = threadIdx.x >> 5;
    float* pre = pat + w * 2112;
    float* pim = pre + 1056;
    size_t p = (size_t)blockIdx.x * 4 + w;
    const __half2* y0 = Y + (size_t)(2 * p) * KP;
    const __half2* y1 = y0 + KP;

#pragma unroll
    for (int u = 0; u <= 16; u++) {
        int k = t + 32 * u;
        if (u < 16 || t == 0) {
            float2 h0 = __half22float2(y0[k]);
            float2 h1 = __half22float2(y1[k]);
            int idx = u * 33 + t;
            pre[idx] = h0.x - h1.y;
            pim[idx] = h0.y + h1.x;
            if (k >= 1 && k < 512) {
                int m = 1024 - k;
                int midx = (m >> 5) * 33 + (m & 31);
                pre[midx] = h0.x + h1.y;
                pim[midx] = h1.x - h0.y;
            }
        }
    }
    __syncwarp();
    float2 v[32];
#pragma unroll
    for (int k1 = 0; k1 < 32; k1++)
        v[k1] = make_float2(pre[k1 * 33 + t], pim[k1 * 33 + t]);
    __syncwarp();
    fft32r<true>(v);
#pragma unroll
    for (int i1 = 1; i1 < 32; i1++)
        v[i1] = cmulc(v[i1], twg[(t * i1) & 1023]);
#pragma unroll
    for (int i1 = 0; i1 < 32; i1++) {
        pre[t * 33 + i1] = v[i1].x;
        pim[t * 33 + i1] = v[i1].y;
    }
    __syncwarp();
#pragma unroll
    for (int k2 = 0; k2 < 32; k2++)
        v[k2] = make_float2(pre[k2 * 33 + t], pim[k2 * 33 + t]);
    __syncwarp();
    fft32r<true>(v);

    const float scl = 1.0f / 1024.0f;
    float m0 = -1e30f, m1 = -1e30f;
#pragma unroll
    for (int i2 = 0; i2 < 32; i2++) {
        v[i2].x *= scl; v[i2].y *= scl;
        m0 = fmaxf(m0, v[i2].x); m1 = fmaxf(m1, v[i2].y);
    }
#pragma unroll
    for (int o = 16; o; o >>= 1) {
        m0 = fmaxf(m0, __shfl_xor_sync(0xffffffffu, m0, o));
        m1 = fmaxf(m1, __shfl_xor_sync(0xffffffffu, m1, o));
    }
    float s0 = 0.f, s1 = 0.f;
    float p0[32], p1[32];
#pragma unroll
    for (int i2 = 0; i2 < 32; i2++) {
        p0[i2] = __expf(v[i2].x - m0);
        p1[i2] = __expf(v[i2].y - m1);
        s0 += p0[i2]; s1 += p1[i2];
    }
#pragma unroll
    for (int o = 16; o; o >>= 1) {
        s0 += __shfl_xor_sync(0xffffffffu, s0, o);
        s1 += __shfl_xor_sync(0xffffffffu, s1, o);
    }
    float inv0 = 1.0f / s0, inv1 = 1.0f / s1;
    __syncwarp();
    __half* hb = (__half*)pre;
#pragma unroll
    for (int i2 = 0; i2 < 32; i2++) {
        int col = t + 32 * i2;
        hb[col] = __float2half(p0[i2] * inv0);
        hb[1024 + col] = __float2half(p1[i2] * inv1);
    }
    __syncwarp();
    uint4* dst = (uint4*)(out16 + (size_t)(2 * p) * 1024);
    const uint4* srcv = (const uint4*)hb;
#pragma unroll
    for (int j = t; j < 256; j += 32) dst[j] = srcv[j];
}

/* ============================== launcher =================================== */
extern "C" void kernel_launch(void* const* d_in, const int* in_sizes, int n_in,
                              void* d_out, int out_size)
{
    const float* query = (const float*)d_in[0];
    const float* Wq    = (const float*)d_in[1];
    const float* bq    = (const float*)d_in[2];
    const float* Wk    = (const float*)d_in[3];
    const float* bk    = (const float*)d_in[4];
    const float* Wv    = (const float*)d_in[5];
    const float* bv    = (const float*)d_in[6];
    const float* Wo    = (const float*)d_in[7];
    const float* bo    = (const float*)d_in[8];
    const float* alpha = (const float*)d_in[9];
    float* out = (float*)d_out;

    __half *pqh, *pql, *pWqh, *pWql, *pWkh, *pWkl, *pWvh, *pWvl, *pWoh, *pWol;
    __half *pc16, *pQ16, *pK16, *pVt16, *pA16;
    __half2 *pSc16, *pFreq;
    float *pV;
    float2 *pTw;
    cudaGetSymbolAddress((void**)&pqh, g_qh);   cudaGetSymbolAddress((void**)&pql, g_ql);
    cudaGetSymbolAddress((void**)&pWqh, g_Wqh); cudaGetSymbolAddress((void**)&pWql, g_Wql);
    cudaGetSymbolAddress((void**)&pWkh, g_Wkh); cudaGetSymbolAddress((void**)&pWkl, g_Wkl);
    cudaGetSymbolAddress((void**)&pWvh, g_Wvh); cudaGetSymbolAddress((void**)&pWvl, g_Wvl);
    cudaGetSymbolAddress((void**)&pWoh, g_Woh); cudaGetSymbolAddress((void**)&pWol, g_Wol);
    cudaGetSymbolAddress((void**)&pQ16, g_Q16);
    cudaGetSymbolAddress((void**)&pK16, g_K16);
    cudaGetSymbolAddress((void**)&pVt16, g_Vt16);
    cudaGetSymbolAddress((void**)&pc16, g_c16);
    cudaGetSymbolAddress((void**)&pV, g_V);
    cudaGetSymbolAddress((void**)&pSc16, g_sc16);
    cudaGetSymbolAddress((void**)&pA16, g_a16);
    cudaGetSymbolAddress((void**)&pFreq, g_freq);
    cudaGetSymbolAddress((void**)&pTw, g_tw);

    const int SM_P = 3 * (2 * 8192 + 2 * 8192);   /* 98304: proj */
    const int SM_S = 3 * (1 * 8192 + 1 * 8192);   /* 49152: scores KIND=2 */
    const int SM_A = 3 * (1 * 8192 + 1 * 4096);   /* 36864: AV KIND=2 */
    const int SM_O = 3 * (1 * 8192 + 2 * 8192);   /* 73728: out-proj KIND=1 */
    cudaFuncSetAttribute((const void*)proj_gemm,
                         cudaFuncAttributeMaxDynamicSharedMemorySize, SM_P);
    cudaFuncSetAttribute((const void*)mma_gemm<1, 4, 2, 128, 2, 4, 64>,
                         cudaFuncAttributeMaxDynamicSharedMemorySize, SM_S);
    cudaFuncSetAttribute((const void*)mma_gemm<2, 5, 2, 64, 4, 2, 1024>,
                         cudaFuncAttributeMaxDynamicSharedMemorySize, SM_A);
    cudaFuncSetAttribute((const void*)mma_gemm<0, 0, 1, 128, 2, 4, 1024>,
                         cudaFuncAttributeMaxDynamicSharedMemorySize, SM_O);

    init_twiddles<<<4, 256>>>(pTw);

    split_convert<<<(int)(NELEM / 4 / 256), 256>>>(query, pqh, pql, (int)(NELEM / 4));
    split_convert_w4<<<dim3(E_ * E_ / 4 / 256, 1, 4), 256>>>(
        Wq, Wk, Wv, Wo, pWqh, pWql, pWkh, pWkl, pWvh, pWvl, pWoh, pWol);

    dim3 gp3(E_ / 128, (B_ * S_) / 128, 3);
    proj_gemm<<<gp3, 256, SM_P>>>(pqh, pql,
                                  pWqh, pWql, pWkh, pWkl, pWvh, pWvl,
                                  bq, bk, bv,
                                  pQ16, pK16, pV);

    transpose_v<<<dim3(32, 2, NBH), dim3(32, 8)>>>(pV, pVt16);

    dim3 gs(S_ / 128, S_ / 128, NBH);
    mma_gemm<1, 4, 2, 128, 2, 4, 64><<<gs, 256, SM_S>>>(
        pQ16, pK16, 0, 0, pSc16, 0.125f);

    fft_rows_fwd_w<<<NBH * S_ / 2 / 4, 128>>>(pSc16, pFreq, pTw);

    fft_cols_w<<<dim3(129, NBH), 128>>>(pFreq, alpha, pTw);

    fft_rows_inv_softmax_w<<<NBH * S_ / 2 / 4, 128>>>(pFreq, pA16, pTw);

    dim3 ga(1, S_ / 128, NBH);
    mma_gemm<2, 5, 2, 64, 4, 2, 1024><<<ga, 256, SM_A>>>(
        pA16, pVt16, 0, 0, pc16, 1.0f);

    dim3 gp(E_ / 128, (B_ * S_) / 128, 1);
    mma_gemm<0, 0, 1, 128, 2, 4, 1024><<<gp, 256, SM_O>>>(
        pc16, pWoh, pWol, bo, out, 1.0f);
}

// round 17
// speedup vs baseline: 1.1818x; 1.0635x over previous
#include <cuda_runtime.h>
#include <cuda_fp16.h>
#include <math.h>
#include <stdint.h>

#define B_   4
#define S_   1024
#define E_   1024
#define H_   16
#define HD_  64
#define NBH  64          /* B*H */
#define KP   528         /* padded half-spectrum width */
#define NELEM ((size_t)B_ * S_ * E_)   /* 4M */

/* ---------------- scratch (device globals: no allocations allowed) -------- */
__device__ __half g_q16[NELEM];                       /* query single fp16  */
__device__ __half g_Wq16[E_*E_], g_Wk16[E_*E_];       /* Wq/Wk single fp16  */
__device__ __half g_Wvh[E_*E_], g_Wvl[E_*E_];
__device__ __half g_Woh[E_*E_], g_Wol[E_*E_];
__device__ __half g_Q16[NELEM];                       /* Q single fp16      */
__device__ __half g_K16[NELEM];                       /* K single fp16      */
__device__ float  g_V[NELEM];
__device__ __half g_Vt16[NELEM];                      /* V^T single fp16    */
__device__ __half2 g_sc16[(size_t)NBH * 512 * 1024];  /* row-pair scores    */
__device__ __half g_a16[(size_t)NBH * S_ * S_];       /* attn fp16          */
__device__ __half g_c16[NELEM];                       /* ctx single fp16    */
__device__ __half2 g_freq[(size_t)NBH * S_ * KP];
__device__ float2 g_tw[1024];

/* ======================= small helpers ==================================== */
__device__ __forceinline__ uint32_t smem_u32(const void* p) {
    uint32_t a;
    asm("{ .reg .u64 t; cvta.to.shared.u64 t, %1; cvt.u32.u64 %0, t; }"
        : "=r"(a) : "l"(p));
    return a;
}
#define CP16(dst, src) \
    asm volatile("cp.async.cg.shared.global [%0], [%1], 16;" \
                 :: "r"(dst), "l"(src))
#define CP_COMMIT() asm volatile("cp.async.commit_group;" ::: "memory")
#define CP_WAIT1()  asm volatile("cp.async.wait_group 1;" ::: "memory")
#define CP_WAIT0()  asm volatile("cp.async.wait_group 0;" ::: "memory")

__device__ __forceinline__ void mma_f16(float* d, const uint32_t* a, const uint32_t* b)
{
    asm volatile(
        "mma.sync.aligned.m16n8k16.row.col.f32.f16.f16.f32 "
        "{%0,%1,%2,%3}, {%4,%5,%6,%7}, {%8,%9}, {%0,%1,%2,%3};"
        : "+f"(d[0]), "+f"(d[1]), "+f"(d[2]), "+f"(d[3])
        : "r"(a[0]), "r"(a[1]), "r"(a[2]), "r"(a[3]), "r"(b[0]), "r"(b[1]));
}

__device__ __forceinline__ int swzt(int row, int ch) {
    return (row << 6) + ((ch ^ ((row >> 1) & 3)) << 4);
}

__device__ __forceinline__ void splitwh(float v, __half& h, __half& l) {
    h = __float2half(v);
    l = __float2half(v - __half2float(h));
}

__device__ __forceinline__ float2 cmul(float2 a, float2 b) {
    return make_float2(a.x * b.x - a.y * b.y, a.x * b.y + a.y * b.x);
}
__device__ __forceinline__ float2 cmulc(float2 a, float2 b) {
    return make_float2(a.x * b.x + a.y * b.y, a.y * b.x - a.x * b.y);
}

/* ===== converts: fp32 -> fp16 single / split (vectorized) ================= */
__device__ __forceinline__ void single_body(const float* src, __half* h, int i)
{
    float4 v = ((const float4*)src)[i];
    __half2 a = __floats2half2_rn(v.x, v.y);
    __half2 b = __floats2half2_rn(v.z, v.w);
    ((uint2*)h)[i] = make_uint2(*(uint32_t*)&a, *(uint32_t*)&b);
}
__device__ __forceinline__ void split_body(const float* src, __half* h,
                                           __half* l, int i)
{
    float4 v = ((const float4*)src)[i];
    __half h0, h1, h2, h3, l0, l1, l2, l3;
    splitwh(v.x, h0, l0); splitwh(v.y, h1, l1);
    splitwh(v.z, h2, l2); splitwh(v.w, h3, l3);
    uint2 hv, lv;
    hv.x = (uint32_t)__half_as_ushort(h0) | ((uint32_t)__half_as_ushort(h1) << 16);
    hv.y = (uint32_t)__half_as_ushort(h2) | ((uint32_t)__half_as_ushort(h3) << 16);
    lv.x = (uint32_t)__half_as_ushort(l0) | ((uint32_t)__half_as_ushort(l1) << 16);
    lv.y = (uint32_t)__half_as_ushort(l2) | ((uint32_t)__half_as_ushort(l3) << 16);
    ((uint2*)h)[i] = hv;
    ((uint2*)l)[i] = lv;
}
__global__ void single_convert(const float* __restrict__ src,
                               __half* __restrict__ h, int n4)
{
    int i = blockIdx.x * blockDim.x + threadIdx.x;
    if (i < n4) single_body(src, h, i);
}
/* weights: z=0 Wq single, z=1 Wk single, z=2 Wv split, z=3 Wo split */
__global__ void conv_w4(
    const float* __restrict__ sq, const float* __restrict__ sk,
    const float* __restrict__ sv, const float* __restrict__ so,
    __half* __restrict__ q16, __half* __restrict__ k16,
    __half* __restrict__ vh, __half* __restrict__ vl,
    __half* __restrict__ oh, __half* __restrict__ ol)
{
    int i = blockIdx.x * blockDim.x + threadIdx.x;
    int z = blockIdx.z;
    if (z == 0)      single_body(sq, q16, i);
    else if (z == 1) single_body(sk, k16, i);
    else if (z == 2) split_body(sv, vh, vl, i);
    else             split_body(so, oh, ol, i);
}

/* ====== batched Q/K/V projection GEMM: one launch, grid.z selects W ======= */
/* z<2 (Q,K): 1 mma (A single x W single), fp16 out.                          */
/* z=2 (V):   2 mma (A single x W split), fp32 out.                           */
__global__ void __launch_bounds__(256, 2) proj_gemm(
    const __half* __restrict__ Ahg,
    const __half* __restrict__ W0h, const __half* __restrict__ W1h,
    const __half* __restrict__ W2h, const __half* __restrict__ W2l,
    const float* __restrict__ bq, const float* __restrict__ bk,
    const float* __restrict__ bv,
    __half* __restrict__ Q16, __half* __restrict__ K16,
    float* __restrict__ Vo)
{
    constexpr int BM = 128, BN = 128;
    constexpr int ATB = BM * 64, BTB = BN * 64;
    constexpr int BUFS = ATB + 2 * BTB;          /* 24576 per stage */
    constexpr int FM = 4, FN = 4;
    constexpr int NIT = 32;

    extern __shared__ char sm[];
    uint32_t smb = smem_u32(sm);

    int tid = threadIdx.x;
    int lane = tid & 31, wid = tid >> 5;
    int wrow = wid >> 2, wcol = wid & 3;
    int m0 = wrow * 64, n0 = wcol * 32;
    int gid = lane >> 2, tig = lane & 3;
    int z = blockIdx.z;

    const __half* Bhg = (z == 0) ? W0h : (z == 1) ? W1h : W2h;
    const float* bias = (z == 0) ? bq : (z == 1) ? bk : bv;
    bool wsplit = (z == 2);

    const char* A8h = (const char*)Ahg + ((size_t)blockIdx.y * BM * 1024) * 2;
    const char* B8h = (const char*)Bhg + ((size_t)blockIdx.x * BN * 1024) * 2;
    const char* B8l = (const char*)W2l + ((size_t)blockIdx.x * BN * 1024) * 2;

    auto fill = [&](int bf, int k0) {
        size_t kb = (size_t)k0 * 2;
        uint32_t base = smb + bf * BUFS;
#pragma unroll
        for (int i = tid; i < BM * 4; i += 256) {
            int r = i >> 2, ch = i & 3;
            size_t so = (size_t)r * 2048 + kb + ch * 16;
            CP16(base + swzt(r, ch), A8h + so);
        }
#pragma unroll
        for (int i = tid; i < BN * 4; i += 256) {
            int r = i >> 2, ch = i & 3;
            size_t so = (size_t)r * 2048 + kb + ch * 16;
            CP16(base + ATB + swzt(r, ch), B8h + so);
            if (wsplit) CP16(base + ATB + BTB + swzt(r, ch), B8l + so);
        }
    };

    float acc[FM][FN][4];
#pragma unroll
    for (int i = 0; i < FM; i++)
#pragma unroll
        for (int j = 0; j < FN; j++)
#pragma unroll
            for (int u = 0; u < 4; u++) acc[i][j][u] = 0.f;

    fill(0, 0);
    CP_COMMIT();
    fill(1, 32);
    CP_COMMIT();

    for (int it = 0; it < NIT; ++it) {
        if (it + 1 < NIT) { CP_WAIT1(); } else { CP_WAIT0(); }
        __syncthreads();
        int buf = it % 3;
        const char* pAh = sm + buf * BUFS;
        const char* pBh = pAh + ATB;
        const char* pBl = pBh + BTB;
#pragma unroll
        for (int ks = 0; ks < 2; ks++) {
            uint32_t bhf[FN][2], blf[FN][2];
#pragma unroll
            for (int fn = 0; fn < FN; fn++) {
                int br = n0 + fn * 8 + gid;
                int o0 = swzt(br, ks * 2) + tig * 4;
                int o1 = swzt(br, ks * 2 + 1) + tig * 4;
                bhf[fn][0] = *(const uint32_t*)(pBh + o0);
                bhf[fn][1] = *(const uint32_t*)(pBh + o1);
                if (wsplit) {
                    blf[fn][0] = *(const uint32_t*)(pBl + o0);
                    blf[fn][1] = *(const uint32_t*)(pBl + o1);
                }
            }
#pragma unroll
            for (int fm = 0; fm < FM; fm++) {
                int ar0 = m0 + fm * 16 + gid, ar8 = ar0 + 8;
                uint32_t ahf[4];
                ahf[0] = *(const uint32_t*)(pAh + swzt(ar0, ks * 2) + tig * 4);
                ahf[1] = *(const uint32_t*)(pAh + swzt(ar8, ks * 2) + tig * 4);
                ahf[2] = *(const uint32_t*)(pAh + swzt(ar0, ks * 2 + 1) + tig * 4);
                ahf[3] = *(const uint32_t*)(pAh + swzt(ar8, ks * 2 + 1) + tig * 4);
                if (wsplit) {
#pragma unroll
                    for (int fn = 0; fn < FN; fn++) {
                        mma_f16(acc[fm][fn], ahf, bhf[fn]);
                        mma_f16(acc[fm][fn], ahf, blf[fn]);
                    }
                } else {
#pragma unroll
                    for (int fn = 0; fn < FN; fn++)
                        mma_f16(acc[fm][fn], ahf, bhf[fn]);
                }
            }
        }
        if (it + 2 < NIT) {
            fill((it + 2) % 3, (it + 2) * 32);
            CP_COMMIT();
        }
    }

    __half* Cout = (z == 0) ? Q16 : K16;
#pragma unroll
    for (int fm = 0; fm < FM; fm++) {
        size_t r0 = (size_t)blockIdx.y * BM + m0 + fm * 16 + gid;
#pragma unroll
        for (int fn = 0; fn < FN; fn++) {
            int cgl = blockIdx.x * BN + n0 + fn * 8 + tig * 2;
            float b0 = bias[cgl], b1 = bias[cgl + 1];
            float v00 = acc[fm][fn][0] + b0;
            float v01 = acc[fm][fn][1] + b1;
            float v10 = acc[fm][fn][2] + b0;
            float v11 = acc[fm][fn][3] + b1;
            if (z == 2) {
                *(float2*)&Vo[r0 * 1024 + cgl] = make_float2(v00, v01);
                *(float2*)&Vo[(r0 + 8) * 1024 + cgl] = make_float2(v10, v11);
            } else {
                __half2 p0 = __floats2half2_rn(v00, v01);
                __half2 p1 = __floats2half2_rn(v10, v11);
                *(uint32_t*)&Cout[r0 * 1024 + cgl] = *(uint32_t*)&p0;
                *(uint32_t*)&Cout[(r0 + 8) * 1024 + cgl] = *(uint32_t*)&p1;
            }
        }
    }
}

/* == generic tensor-core GEMM (scores / AV / out), 3-stage pipeline ======== */
/* KIND 1: A single x B split (2 mma). KIND 2: single x single (1 mma).       */
/* EPI 0: fp32+bias; 4: half2 row-pair scores; 5: single fp16.                */
template<int MODE, int EPI, int KIND, int BN, int WROWS, int WCOLS, int KTOT>
__global__ void __launch_bounds__(256, 2) mma_gemm(
    const __half* __restrict__ Ahg,
    const __half* __restrict__ Bhg, const __half* __restrict__ Blg,
    const float* __restrict__ bias, void* __restrict__ Cp,
    float oscale)
{
    constexpr int BM = 128;
    constexpr int ATB = BM * 64;
    constexpr int BTB = BN * 64;
    constexpr int NB = (KIND == 2) ? 1 : 2;
    constexpr int BUFS = ATB + NB * BTB;
    constexpr int WTM = BM / WROWS, WTN = BN / WCOLS;
    constexpr int FM = WTM / 16, FN = WTN / 8;
    constexpr int NIT = KTOT / 32;

    extern __shared__ char sm[];
    uint32_t smb = smem_u32(sm);

    int tid = threadIdx.x;
    int lane = tid & 31, wid = tid >> 5;
    int wrow = wid / WCOLS, wcol = wid % WCOLS;
    int m0 = wrow * WTM, n0 = wcol * WTN;
    int gid = lane >> 2, tig = lane & 3;

    size_t offA = 0, offB = 0, offC = 0, offP = 0;
    if (MODE == 1) {
        int z = blockIdx.z;
        size_t ho = (size_t)(z >> 4) * S_ * E_ + (size_t)(z & 15) * HD_;
        offA = ho; offB = ho;
        offP = (size_t)z * 512 * 1024;
    } else if (MODE == 2) {
        int z = blockIdx.z;
        offA = (size_t)z * S_ * S_;
        offB = (size_t)z * HD_ * S_;
        offC = (size_t)(z >> 4) * S_ * E_ + (size_t)(z & 15) * HD_;
    }
    const char* A8h = (const char*)Ahg + (offA + (size_t)blockIdx.y * BM * 1024) * 2;
    const char* B8h = (const char*)Bhg + (offB + (size_t)blockIdx.x * BN * 1024) * 2;
    const char* B8l = (const char*)Blg + (offB + (size_t)blockIdx.x * BN * 1024) * 2;

    auto fill = [&](int bf, int k0) {
        size_t kb = (size_t)k0 * 2;
        uint32_t base = smb + bf * BUFS;
#pragma unroll
        for (int i = tid; i < BM * 4; i += 256) {
            int r = i >> 2, ch = i & 3;
            size_t so = (size_t)r * 2048 + kb + ch * 16;
            CP16(base + swzt(r, ch), A8h + so);
        }
#pragma unroll
        for (int i = tid; i < BN * 4; i += 256) {
            int r = i >> 2, ch = i & 3;
            size_t so = (size_t)r * 2048 + kb + ch * 16;
            CP16(base + ATB + swzt(r, ch), B8h + so);
            if (KIND != 2) CP16(base + ATB + BTB + swzt(r, ch), B8l + so);
        }
    };

    float acc[FM][FN][4];
#pragma unroll
    for (int i = 0; i < FM; i++)
#pragma unroll
        for (int j = 0; j < FN; j++)
#pragma unroll
            for (int u = 0; u < 4; u++) acc[i][j][u] = 0.f;

    fill(0, 0);
    CP_COMMIT();
    if (NIT > 1) fill(1, 32);
    CP_COMMIT();

    for (int it = 0; it < NIT; ++it) {
        if (it + 1 < NIT) { CP_WAIT1(); } else { CP_WAIT0(); }
        __syncthreads();
        int buf = it % 3;
        const char* pAh = sm + buf * BUFS;
        const char* pBh = pAh + ATB;
        const char* pBl = pBh + BTB;
#pragma unroll
        for (int ks = 0; ks < 2; ks++) {
            uint32_t bhf[FN][2], blf[FN][2];
#pragma unroll
            for (int fn = 0; fn < FN; fn++) {
                int br = n0 + fn * 8 + gid;
                int o0 = swzt(br, ks * 2) + tig * 4;
                int o1 = swzt(br, ks * 2 + 1) + tig * 4;
                bhf[fn][0] = *(const uint32_t*)(pBh + o0);
                bhf[fn][1] = *(const uint32_t*)(pBh + o1);
                if (KIND != 2) {
                    blf[fn][0] = *(const uint32_t*)(pBl + o0);
                    blf[fn][1] = *(const uint32_t*)(pBl + o1);
                }
            }
#pragma unroll
            for (int fm = 0; fm < FM; fm++) {
                int ar0 = m0 + fm * 16 + gid, ar8 = ar0 + 8;
                uint32_t ahf[4];
                ahf[0] = *(const uint32_t*)(pAh + swzt(ar0, ks * 2) + tig * 4);
                ahf[1] = *(const uint32_t*)(pAh + swzt(ar8, ks * 2) + tig * 4);
                ahf[2] = *(const uint32_t*)(pAh + swzt(ar0, ks * 2 + 1) + tig * 4);
                ahf[3] = *(const uint32_t*)(pAh + swzt(ar8, ks * 2 + 1) + tig * 4);
                if (KIND == 1) {
#pragma unroll
                    for (int fn = 0; fn < FN; fn++) {
                        mma_f16(acc[fm][fn], ahf, bhf[fn]);
                        mma_f16(acc[fm][fn], ahf, blf[fn]);
                    }
                } else {
#pragma unroll
                    for (int fn = 0; fn < FN; fn++)
                        mma_f16(acc[fm][fn], ahf, bhf[fn]);
                }
            }
        }
        if (it + 2 < NIT) {
            fill((it + 2) % 3, (it + 2) * 32);
            CP_COMMIT();
        }
    }

#pragma unroll
    for (int fm = 0; fm < FM; fm++) {
        size_t r0 = (size_t)blockIdx.y * BM + m0 + fm * 16 + gid;
#pragma unroll
        for (int fn = 0; fn < FN; fn++) {
            int cgl = blockIdx.x * BN + n0 + fn * 8 + tig * 2;
            float v00 = acc[fm][fn][0] * oscale;
            float v01 = acc[fm][fn][1] * oscale;
            float v10 = acc[fm][fn][2] * oscale;
            float v11 = acc[fm][fn][3] * oscale;
            if (EPI == 4) {
                float q00 = __shfl_xor_sync(0xffffffffu, v00, 4);
                float q01 = __shfl_xor_sync(0xffffffffu, v01, 4);
                float q10 = __shfl_xor_sync(0xffffffffu, v10, 4);
                float q11 = __shfl_xor_sync(0xffffffffu, v11, 4);
                if (!(gid & 1)) {
                    __half2* SC = (__half2*)Cp;
                    __half2 a0 = __floats2half2_rn(v00, q00);
                    __half2 a1 = __floats2half2_rn(v01, q01);
                    __half2 b0 = __floats2half2_rn(v10, q10);
                    __half2 b1 = __floats2half2_rn(v11, q11);
                    uint2 pk0 = make_uint2(*(uint32_t*)&a0, *(uint32_t*)&a1);
                    uint2 pk1 = make_uint2(*(uint32_t*)&b0, *(uint32_t*)&b1);
                    *(uint2*)&SC[offP + (r0 >> 1) * 1024 + cgl] = pk0;
                    *(uint2*)&SC[offP + ((r0 + 8) >> 1) * 1024 + cgl] = pk1;
                }
            } else if (EPI == 0) {
                float b0 = bias[cgl], b1 = bias[cgl + 1];
                float* C = (float*)Cp;
                *(float2*)&C[offC + r0 * 1024 + cgl] = make_float2(v00 + b0, v01 + b1);
                *(float2*)&C[offC + (r0 + 8) * 1024 + cgl] = make_float2(v10 + b0, v11 + b1);
            } else {
                __half* Ch = (__half*)Cp;
                __half2 p0 = __floats2half2_rn(v00, v01);
                __half2 p1 = __floats2half2_rn(v10, v11);
                *(uint32_t*)&Ch[offC + r0 * 1024 + cgl] = *(uint32_t*)&p0;
                *(uint32_t*)&Ch[offC + (r0 + 8) * 1024 + cgl] = *(uint32_t*)&p1;
            }
        }
    }
}

/* ===== Vt[z][d][k] = V[b][k][h*64+d], written single fp16 ================= */
__global__ void transpose_v(const float* __restrict__ V, __half* __restrict__ Vt)
{
    __shared__ float tile[32][33];
    int z = blockIdx.z;
    int b = z >> 4, h = z & 15;
    int k0 = blockIdx.x * 32, d0 = blockIdx.y * 32;
    int tx = threadIdx.x, ty = threadIdx.y;
#pragma unroll
    for (int i = 0; i < 4; i++)
        tile[ty + i * 8][tx] =
            V[((size_t)b * S_ + k0 + ty + i * 8) * E_ + h * HD_ + d0 + tx];
    __syncthreads();
#pragma unroll
    for (int i = 0; i < 4; i++) {
        size_t o = ((size_t)z * HD_ + d0 + ty + i * 8) * S_ + k0 + tx;
        Vt[o] = __float2half(tile[tx][ty + i * 8]);
    }
}

/* ===================== twiddle init ======================================= */
__global__ void init_twiddles(float2* tw)
{
    int j = blockIdx.x * blockDim.x + threadIdx.x;
    if (j < 1024) {
        float ang = -6.28318530717958647692f * (float)j / 1024.0f;
        tw[j] = make_float2(cosf(ang), sinf(ang));
    }
}

/* ============== in-register 32-pt FFT (DIF, natural order out) ============ */
template<bool INV>
__device__ __forceinline__ void fft32r(float2* v)
{
    const float C[16] = {
        1.f, 0.980785280403230f, 0.923879532511287f, 0.831469612302545f,
        0.707106781186548f, 0.555570233019602f, 0.382683432365090f, 0.195090322016128f,
        0.f, -0.195090322016128f, -0.382683432365090f, -0.555570233019602f,
        -0.707106781186548f, -0.831469612302545f, -0.923879532511287f, -0.980785280403230f };
    const float Sn[16] = {
        0.f, 0.195090322016128f, 0.382683432365090f, 0.555570233019602f,
        0.707106781186548f, 0.831469612302545f, 0.923879532511287f, 0.980785280403230f,
        1.f, 0.980785280403230f, 0.923879532511287f, 0.831469612302545f,
        0.707106781186548f, 0.555570233019602f, 0.382683432365090f, 0.195090322016128f };
#pragma unroll
    for (int h = 16; h >= 1; h >>= 1) {
#pragma unroll
        for (int b = 0; b < 32; b += 2 * h) {
#pragma unroll
            for (int j = 0; j < h; j++) {
                int e = j * (16 / h);
                float tc = C[e];
                float ts = INV ? Sn[e] : -Sn[e];
                float2 a = v[b + j], bb = v[b + j + h];
                v[b + j] = make_float2(a.x + bb.x, a.y + bb.y);
                float dx = a.x - bb.x, dy = a.y - bb.y;
                v[b + j + h] = make_float2(dx * tc - dy * ts, dx * ts + dy * tc);
            }
        }
    }
#pragma unroll
    for (int i = 0; i < 32; i++) {
        int r = ((i & 1) << 4) | ((i & 2) << 2) | (i & 4) | ((i & 8) >> 2) | ((i & 16) >> 4);
        if (r > i) { float2 tmp = v[i]; v[i] = v[r]; v[r] = tmp; }
    }
}

/* ====== pass 1: warp fwd FFT of packed fp16 row pairs -> half spectra ===== */
__global__ void __launch_bounds__(128) fft_rows_fwd_w(
    const __half2* __restrict__ sc, __half2* __restrict__ Y,
    const float2* __restrict__ twg)
{
    __shared__ __align__(16) float pat[4 * 2112];
    int t = threadIdx.x & 31, w = threadIdx.x >> 5;
    float* pre = pat + w * 2112;
    float* pim = pre + 1056;
    size_t p = (size_t)blockIdx.x * 4 + w;
    const __half2* r01 = sc + p * 1024;

    float2 v[32];
#pragma unroll
    for (int i2 = 0; i2 < 32; i2++)
        v[i2] = __half22float2(r01[t + 32 * i2]);
    fft32r<false>(v);
#pragma unroll
    for (int k2 = 1; k2 < 32; k2++)
        v[k2] = cmul(v[k2], twg[(t * k2) & 1023]);
#pragma unroll
    for (int k2 = 0; k2 < 32; k2++) {
        pre[t * 33 + k2] = v[k2].x;
        pim[t * 33 + k2] = v[k2].y;
    }
    __syncwarp();
#pragma unroll
    for (int i1 = 0; i1 < 32; i1++)
        v[i1] = make_float2(pre[i1 * 33 + t], pim[i1 * 33 + t]);
    __syncwarp();
    fft32r<false>(v);
#pragma unroll
    for (int k1 = 0; k1 < 32; k1++) {
        pre[k1 * 33 + t] = v[k1].x;
        pim[k1 * 33 + t] = v[k1].y;
    }
    __syncwarp();

    __half2* y0 = Y + (size_t)(2 * p) * KP;
    __half2* y1 = y0 + KP;
#pragma unroll
    for (int u = 0; u <= 16; u++) {
        int k = t + 32 * u;
        if (u < 16 || t == 0) {
            int idx = u * 33 + t;
            float2 Xk = make_float2(pre[idx], pim[idx]);
            int m = (1024 - k) & 1023;
            int midx = (m >> 5) * 33 + (m & 31);
            float2 Xm = make_float2(pre[midx], pim[midx]);
            y0[k] = __floats2half2_rn(0.5f * (Xk.x + Xm.x), 0.5f * (Xk.y - Xm.y));
            y1[k] = __floats2half2_rn(0.5f * (Xk.y + Xm.y), 0.5f * (Xm.x - Xk.x));
        }
    }
}

/* ===== pass 2: warp-level col FFT + real cos-filter + col IFFT =========== */
__global__ void __launch_bounds__(128) fft_cols_w(
    __half2* __restrict__ Y, const float* __restrict__ alpha_p,
    const float2* __restrict__ twg)
{
    __shared__ __align__(16) float sm[10240];   /* slab 2x5120 / patches 4x2112 */
    float* slab_re = sm;
    float* slab_im = sm + 5120;
    int tid = threadIdx.x;
    int t = tid & 31, w = tid >> 5;
    int z = blockIdx.y;
    int kbase = blockIdx.x * 4;
    __half2* base = Y + (size_t)z * S_ * KP + kbase;

#pragma unroll 8
    for (int idx = tid; idx < 4096; idx += 128) {
        int q = idx >> 2, c = idx & 3;
        float2 val = __half22float2(base[(size_t)q * KP + c]);
        slab_re[q * 5 + c] = val.x;
        slab_im[q * 5 + c] = val.y;
    }
    __syncthreads();

    float2 v[32];
#pragma unroll
    for (int i2 = 0; i2 < 32; i2++) {
        int q = t + 32 * i2;
        v[i2] = make_float2(slab_re[q * 5 + w], slab_im[q * 5 + w]);
    }
    __syncthreads();
    float* pre = sm + w * 2112;
    float* pim = pre + 1056;

    fft32r<false>(v);
#pragma unroll
    for (int k2 = 1; k2 < 32; k2++)
        v[k2] = cmul(v[k2], twg[(t * k2) & 1023]);
#pragma unroll
    for (int k2 = 0; k2 < 32; k2++) {
        pre[t * 33 + k2] = v[k2].x;
        pim[t * 33 + k2] = v[k2].y;
    }
    __syncwarp();
#pragma unroll
    for (int i1 = 0; i1 < 32; i1++)
        v[i1] = make_float2(pre[i1 * 33 + t], pim[i1 * 33 + t]);
    __syncwarp();
    fft32r<false>(v);

    float alpha = *alpha_p;
#pragma unroll
    for (int k1 = 0; k1 < 32; k1++) {
        float mag = sqrtf(v[k1].x * v[k1].x + v[k1].y * v[k1].y);
        float g = __cosf(alpha * atanf(__logf(mag + 1e-10f)));
        v[k1].x *= g; v[k1].y *= g;
    }

    fft32r<true>(v);
#pragma unroll
    for (int i1 = 1; i1 < 32; i1++)
        v[i1] = cmulc(v[i1], twg[(t * i1) & 1023]);
#pragma unroll
    for (int i1 = 0; i1 < 32; i1++) {
        pre[t * 33 + i1] = v[i1].x;
        pim[t * 33 + i1] = v[i1].y;
    }
    __syncwarp();
#pragma unroll
    for (int k2 = 0; k2 < 32; k2++)
        v[k2] = make_float2(pre[k2 * 33 + t], pim[k2 * 33 + t]);
    __syncwarp();
    fft32r<true>(v);

    __syncthreads();
    const float scl = 1.0f / 1024.0f;
#pragma unroll
    for (int i2 = 0; i2 < 32; i2++) {
        int q = t + 32 * i2;
        slab_re[q * 5 + w] = v[i2].x * scl;
        slab_im[q * 5 + w] = v[i2].y * scl;
    }
    __syncthreads();
#pragma unroll 8
    for (int idx = tid; idx < 4096; idx += 128) {
        int q = idx >> 2, c = idx & 3;
        if (kbase + c < 513)
            base[(size_t)q * KP + c] =
                __floats2half2_rn(slab_re[q * 5 + c], slab_im[q * 5 + c]);
    }
}

/* == pass 3: warp c2r inverse + warp softmax, attn fp16 vectorized out ===== */
__global__ void __launch_bounds__(128) fft_rows_inv_softmax_w(
    const __half2* __restrict__ Y, __half* __restrict__ out16,
    const float2* __restrict__ twg)
{
    __shared__ __align__(16) float pat[4 * 2112];
    int t = threadIdx.x & 31, w = threadIdx.x >> 5;
    float* pre = pat + w * 2112;
    float* pim = pre + 1056;
    size_t p = (size_t)blockIdx.x * 4 + w;
    const __half2* y0 = Y + (size_t)(2 * p) * KP;
    const __half2* y1 = y0 + KP;

#pragma unroll
    for (int u = 0; u <= 16; u++) {
        int k = t + 32 * u;
        if (u < 16 || t == 0) {
            float2 h0 = __half22float2(y0[k]);
            float2 h1 = __half22float2(y1[k]);
            int idx = u * 33 + t;
            pre[idx] = h0.x - h1.y;
            pim[idx] = h0.y + h1.x;
            if (k >= 1 && k < 512) {
                int m = 1024 - k;
                int midx = (m >> 5) * 33 + (m & 31);
                pre[midx] = h0.x + h1.y;
                pim[midx] = h1.x - h0.y;
            }
        }
    }
    __syncwarp();
    float2 v[32];
#pragma unroll
    for (int k1 = 0; k1 < 32; k1++)
        v[k1] = make_float2(pre[k1 * 33 + t], pim[k1 * 33 + t]);
    __syncwarp();
    fft32r<true>(v);
#pragma unroll
    for (int i1 = 1; i1 < 32; i1++)
        v[i1] = cmulc(v[i1], twg[(t * i1) & 1023]);
#pragma unroll
    for (int i1 = 0; i1 < 32; i1++) {
        pre[t * 33 + i1] = v[i1].x;
        pim[t * 33 + i1] = v[i1].y;
    }
    __syncwarp();
#pragma unroll
    for (int k2 = 0; k2 < 32; k2++)
        v[k2] = make_float2(pre[k2 * 33 + t], pim[k2 * 33 + t]);
    __syncwarp();
    fft32r<true>(v);

    const float scl = 1.0f / 1024.0f;
    float m0 = -1e30f, m1 = -1e30f;
#pragma unroll
    for (int i2 = 0; i2 < 32; i2++) {
        v[i2].x *= scl; v[i2].y *= scl;
        m0 = fmaxf(m0, v[i2].x); m1 = fmaxf(m1, v[i2].y);
    }
#pragma unroll
    for (int o = 16; o; o >>= 1) {
        m0 = fmaxf(m0, __shfl_xor_sync(0xffffffffu, m0, o));
        m1 = fmaxf(m1, __shfl_xor_sync(0xffffffffu, m1, o));
    }
    float s0 = 0.f, s1 = 0.f;
    float p0[32], p1[32];
#pragma unroll
    for (int i2 = 0; i2 < 32; i2++) {
        p0[i2] = __expf(v[i2].x - m0);
        p1[i2] = __expf(v[i2].y - m1);
        s0 += p0[i2]; s1 += p1[i2];
    }
#pragma unroll
    for (int o = 16; o; o >>= 1) {
        s0 += __shfl_xor_sync(0xffffffffu, s0, o);
        s1 += __shfl_xor_sync(0xffffffffu, s1, o);
    }
    float inv0 = 1.0f / s0, inv1 = 1.0f / s1;
    __syncwarp();
    __half* hb = (__half*)pre;
#pragma unroll
    for (int i2 = 0; i2 < 32; i2++) {
        int col = t + 32 * i2;
        hb[col] = __float2half(p0[i2] * inv0);
        hb[1024 + col] = __float2half(p1[i2] * inv1);
    }
    __syncwarp();
    uint4* dst = (uint4*)(out16 + (size_t)(2 * p) * 1024);
    const uint4* srcv = (const uint4*)hb;
#pragma unroll
    for (int j = t; j < 256; j += 32) dst[j] = srcv[j];
}

/* ============================== launcher =================================== */
extern "C" void kernel_launch(void* const* d_in, const int* in_sizes, int n_in,
                              void* d_out, int out_size)
{
    const float* query = (const float*)d_in[0];
    const float* Wq    = (const float*)d_in[1];
    const float* bq    = (const float*)d_in[2];
    const float* Wk    = (const float*)d_in[3];
    const float* bk    = (const float*)d_in[4];
    const float* Wv    = (const float*)d_in[5];
    const float* bv    = (const float*)d_in[6];
    const float* Wo    = (const float*)d_in[7];
    const float* bo    = (const float*)d_in[8];
    const float* alpha = (const float*)d_in[9];
    float* out = (float*)d_out;

    __half *pq16, *pWq16, *pWk16, *pWvh, *pWvl, *pWoh, *pWol;
    __half *pc16, *pQ16, *pK16, *pVt16, *pA16;
    __half2 *pSc16, *pFreq;
    float *pV;
    float2 *pTw;
    cudaGetSymbolAddress((void**)&pq16, g_q16);
    cudaGetSymbolAddress((void**)&pWq16, g_Wq16);
    cudaGetSymbolAddress((void**)&pWk16, g_Wk16);
    cudaGetSymbolAddress((void**)&pWvh, g_Wvh); cudaGetSymbolAddress((void**)&pWvl, g_Wvl);
    cudaGetSymbolAddress((void**)&pWoh, g_Woh); cudaGetSymbolAddress((void**)&pWol, g_Wol);
    cudaGetSymbolAddress((void**)&pQ16, g_Q16);
    cudaGetSymbolAddress((void**)&pK16, g_K16);
    cudaGetSymbolAddress((void**)&pVt16, g_Vt16);
    cudaGetSymbolAddress((void**)&pc16, g_c16);
    cudaGetSymbolAddress((void**)&pV, g_V);
    cudaGetSymbolAddress((void**)&pSc16, g_sc16);
    cudaGetSymbolAddress((void**)&pA16, g_a16);
    cudaGetSymbolAddress((void**)&pFreq, g_freq);
    cudaGetSymbolAddress((void**)&pTw, g_tw);

    const int SM_P = 3 * (1 * 8192 + 2 * 8192);   /* 73728: proj */
    const int SM_S = 3 * (1 * 8192 + 1 * 8192);   /* 49152: scores KIND=2 */
    const int SM_A = 3 * (1 * 8192 + 1 * 4096);   /* 36864: AV KIND=2 */
    const int SM_O = 3 * (1 * 8192 + 2 * 8192);   /* 73728: out-proj KIND=1 */
    cudaFuncSetAttribute((const void*)proj_gemm,
                         cudaFuncAttributeMaxDynamicSharedMemorySize, SM_P);
    cudaFuncSetAttribute((const void*)mma_gemm<1, 4, 2, 128, 2, 4, 64>,
                         cudaFuncAttributeMaxDynamicSharedMemorySize, SM_S);
    cudaFuncSetAttribute((const void*)mma_gemm<2, 5, 2, 64, 4, 2, 1024>,
                         cudaFuncAttributeMaxDynamicSharedMemorySize, SM_A);
    cudaFuncSetAttribute((const void*)mma_gemm<0, 0, 1, 128, 2, 4, 1024>,
                         cudaFuncAttributeMaxDynamicSharedMemorySize, SM_O);

    init_twiddles<<<4, 256>>>(pTw);

    single_convert<<<(int)(NELEM / 4 / 256), 256>>>(query, pq16, (int)(NELEM / 4));
    conv_w4<<<dim3(E_ * E_ / 4 / 256, 1, 4), 256>>>(
        Wq, Wk, Wv, Wo, pWq16, pWk16, pWvh, pWvl, pWoh, pWol);

    dim3 gp3(E_ / 128, (B_ * S_) / 128, 3);
    proj_gemm<<<gp3, 256, SM_P>>>(pq16, pWq16, pWk16, pWvh, pWvl,
                                  bq, bk, bv, pQ16, pK16, pV);

    transpose_v<<<dim3(32, 2, NBH), dim3(32, 8)>>>(pV, pVt16);

    dim3 gs(S_ / 128, S_ / 128, NBH);
    mma_gemm<1, 4, 2, 128, 2, 4, 64><<<gs, 256, SM_S>>>(
        pQ16, pK16, 0, 0, pSc16, 0.125f);

    fft_rows_fwd_w<<<NBH * S_ / 2 / 4, 128>>>(pSc16, pFreq, pTw);

    fft_cols_w<<<dim3(129, NBH), 128>>>(pFreq, alpha, pTw);

    fft_rows_inv_softmax_w<<<NBH * S_ / 2 / 4, 128>>>(pFreq, pA16, pTw);

    dim3 ga(1, S_ / 128, NBH);
    mma_gemm<2, 5, 2, 64, 4, 2, 1024><<<ga, 256, SM_A>>>(
        pA16, pVt16, 0, 0, pc16, 1.0f);

    dim3 gp(E_ / 128, (B_ * S_) / 128, 1);
    mma_gemm<0, 0, 1, 128, 2, 4, 1024><<<gp, 256, SM_O>>>(
        pc16, pWoh, pWol, bo, out, 1.0f);
}